// round 13
// baseline (speedup 1.0000x reference)
#include <cuda_runtime.h>
#include <cuda_bf16.h>
#include <math.h>
#include <stdint.h>

// Problem constants
#define NB    2
#define NT    2048
#define ND    768
#define NH    12
#define NHS   64
#define NFF   3072
#define NHALF 1536
#define NBT   (NB*NT)   // 4096

// ---------------- scratch (device globals; no allocation) ----------------
__device__ __nv_bfloat16 g_h   [NBT * ND];
__device__ __nv_bfloat16 g_qkv [NBT * 3 * ND];
__device__ __nv_bfloat16 g_attn[NBT * ND];
__device__ float         g_x1  [NBT * ND];
__device__ __nv_bfloat16 g_gl  [NBT * NHALF];
__device__ __nv_bfloat16 g_wqkv_t[3 * ND * ND];   // [2304 n][768 k]
__device__ __nv_bfloat16 g_wo_t  [ND * ND];       // [768 n][768 k]
__device__ __nv_bfloat16 g_w1_t  [NFF * ND];      // [3072 packed n][768 k]
__device__ __nv_bfloat16 g_w2_t  [ND * NHALF];    // [768 n][1536 k]

// ---------------- async copy helpers ----------------
__device__ __forceinline__ void cp_async16(void* smem_dst, const void* gmem_src)
{
    uint32_t d = (uint32_t)__cvta_generic_to_shared(smem_dst);
    asm volatile("cp.async.cg.shared.global [%0], [%1], 16;\n" :: "r"(d), "l"(gmem_src));
}
#define CP_COMMIT() asm volatile("cp.async.commit_group;\n" ::: "memory")
#define CP_WAIT1()  asm volatile("cp.async.wait_group 1;\n" ::: "memory")
#define CP_WAIT0()  asm volatile("cp.async.wait_group 0;\n" ::: "memory")

// ---------------- ldmatrix ----------------
__device__ __forceinline__ void ldsm_x4(uint32_t& r0, uint32_t& r1,
                                        uint32_t& r2, uint32_t& r3, uint32_t addr)
{
    asm volatile("ldmatrix.sync.aligned.m8n8.x4.shared.b16 {%0,%1,%2,%3}, [%4];"
                 : "=r"(r0), "=r"(r1), "=r"(r2), "=r"(r3) : "r"(addr));
}
__device__ __forceinline__ void ldsm_x4_t(uint32_t& r0, uint32_t& r1,
                                          uint32_t& r2, uint32_t& r3, uint32_t addr)
{
    asm volatile("ldmatrix.sync.aligned.m8n8.x4.trans.shared.b16 {%0,%1,%2,%3}, [%4];"
                 : "=r"(r0), "=r"(r1), "=r"(r2), "=r"(r3) : "r"(addr));
}

// ---------------- BF16 MMA ----------------
__device__ __forceinline__ void mma_bf16(float* c, const uint32_t* a, const uint32_t* b)
{
    asm volatile(
        "mma.sync.aligned.m16n8k16.row.col.f32.bf16.bf16.f32 "
        "{%0,%1,%2,%3}, {%4,%5,%6,%7}, {%8,%9}, {%0,%1,%2,%3};\n"
        : "+f"(c[0]), "+f"(c[1]), "+f"(c[2]), "+f"(c[3])
        : "r"(a[0]), "r"(a[1]), "r"(a[2]), "r"(a[3]), "r"(b[0]), "r"(b[1]));
}

__device__ __forceinline__ uint32_t packbf(float lo, float hi)
{
    __nv_bfloat162 p = __floats2bfloat162_rn(lo, hi);
    return *(uint32_t*)&p;
}

__device__ __forceinline__ float siluf(float z)
{
    return z / (1.0f + __expf(-z));
}

// ---------------- pack Wq/Wk/Wv -> [2304 n][768 k] bf16 ----------------
__global__ void pack_wqkv_kernel(const float* __restrict__ Wq,
                                 const float* __restrict__ Wk,
                                 const float* __restrict__ Wv)
{
    int idx = blockIdx.x * blockDim.x + threadIdx.x;
    const int total = 3 * ND * ND;
    if (idx >= total) return;
    int n = idx / ND;
    int d = idx % ND;
    int m = n / ND;
    int r = n % ND;
    int h = r / NHS;
    int k = r % NHS;
    const float* W = (m == 0) ? Wq : ((m == 1) ? Wk : Wv);
    g_wqkv_t[idx] = __float2bfloat16(W[h * ND * NHS + d * NHS + k]);
}

// ---------------- transpose + bf16 Wo/W1(swiglu-packed)/W2 ----------------
#define WO_N (ND * ND)
#define W1_N (ND * NFF)
#define W2_N (NHALF * ND)
__global__ void round_weights_kernel(const float* __restrict__ Wo,
                                     const float* __restrict__ W1,
                                     const float* __restrict__ W2)
{
    int idx = blockIdx.x * blockDim.x + threadIdx.x;
    if (idx < WO_N) {
        int n = idx / ND, k = idx % ND;
        g_wo_t[idx] = __float2bfloat16(Wo[k * ND + n]);
    }
    if (idx < W1_N) {
        int p = idx / ND, k = idx % ND;
        int base128 = p & ~127;
        int loc = p & 127;
        int u = loc >> 4;
        int v = loc & 15;
        int fbase = (base128 >> 1) + u * 8;
        int src = (v < 8) ? (fbase + v) : (NHALF + fbase + (v - 8));
        g_w1_t[idx] = __float2bfloat16(W1[k * NFF + src]);
    }
    if (idx < W2_N) {
        int n = idx / NHALF, k = idx % NHALF;
        g_w2_t[idx] = __float2bfloat16(W2[k * ND + n]);
    }
}

// ---------------- RMSNorm (bf16 output) ----------------
__device__ __forceinline__ void rms_body(const float* __restrict__ in,
                                         __nv_bfloat16* __restrict__ out,
                                         const float* __restrict__ g)
{
    int tid = threadIdx.x;
    float v0 = in[tid], v1 = in[tid + 256], v2 = in[tid + 512];
    float ss = v0*v0 + v1*v1 + v2*v2;
    #pragma unroll
    for (int o = 16; o; o >>= 1) ss += __shfl_xor_sync(0xffffffffu, ss, o);
    __shared__ float ws[8];
    __shared__ float s_inv;
    if ((tid & 31) == 0) ws[tid >> 5] = ss;
    __syncthreads();
    if (tid == 0) {
        float t = 0.f;
        #pragma unroll
        for (int i = 0; i < 8; i++) t += ws[i];
        float rms = sqrtf(t * (1.0f / (float)ND));
        s_inv = 1.0f / (rms + 1e-8f);
    }
    __syncthreads();
    float inv = s_inv;
    out[tid]       = __float2bfloat16(g[tid]       * v0 * inv);
    out[tid + 256] = __float2bfloat16(g[tid + 256] * v1 * inv);
    out[tid + 512] = __float2bfloat16(g[tid + 512] * v2 * inv);
}

__global__ __launch_bounds__(256) void rmsnorm1_kernel(const float* __restrict__ x,
                                                       const float* __restrict__ g)
{
    int row = blockIdx.x;
    rms_body(x + (size_t)row * ND, g_h + (size_t)row * ND, g);
}

__global__ __launch_bounds__(256) void rmsnorm2_kernel(const float* __restrict__ g)
{
    int row = blockIdx.x;
    rms_body(g_x1 + (size_t)row * ND, g_h + (size_t)row * ND, g);
}

// ---------------- BF16 GEMM: 128x64 tile, 128 threads, 2-stage cp.async ---
// Warp-tile 32x64 (wm=warp*32, wn=0): A-fragments read ONCE per warp-row.
// 4 CTAs/SM (smem 55.3KB, ~110 regs) -> cross-CTA latency hiding.
// MODE: 0 = fp32 out (+bias/res), 1 = bf16 out, 2 = fused-swiglu bf16 out
#define KC 64
#define STR32 36
#define A_STG32 (128 * STR32)          // 4608 b32
#define B_STG32 (64 * STR32)           // 2304 b32
#define GEMM_SMEM ((2 * A_STG32 + 2 * B_STG32) * 4)   // 55296 B

template<int N, int K, bool BIAS, bool RES, int MODE, typename OutT>
__device__ __forceinline__ void bf16_gemm_body(const __nv_bfloat16* __restrict__ A,
                                               const __nv_bfloat16* __restrict__ Bt,
                                               OutT* __restrict__ C,
                                               const float* __restrict__ bias,
                                               const float* __restrict__ res)
{
    extern __shared__ __align__(16) uint32_t smu[];
    uint32_t* As = smu;                 // [2][128][36] b32
    uint32_t* Bs = smu + 2 * A_STG32;   // [2][64][36] b32

    const int tid  = threadIdx.x;
    const int warp = tid >> 5, lane = tid & 31;
    const int wm = warp * 32;
    const int bm = blockIdx.y * 128;
    const int bn = blockIdx.x * 64;

    const uint32_t s_smu = (uint32_t)__cvta_generic_to_shared(smu);

    const int brow = tid >> 1;          // B loader row 0..63
    const int bchb = (tid & 1) * 4;     // B chunk base

    const uint32_t a_off0 = (uint32_t)(wm + (lane & 15)) * 144u + ((lane >> 4) << 4);
    const uint32_t b_off0 = (uint32_t)((lane & 7) + ((lane >> 4) << 3)) * 144u
                          + (((lane >> 3) & 1) << 4);

    float acc[2][8][4];
    #pragma unroll
    for (int i = 0; i < 2; i++)
        #pragma unroll
        for (int j = 0; j < 8; j++)
            #pragma unroll
            for (int t = 0; t < 4; t++) acc[i][j][t] = 0.f;

    const int NCH = K / KC;

    // stage 0
    {
        uint32_t* as = As;
        uint32_t* bs = Bs;
        #pragma unroll
        for (int ch = 0; ch < 8; ch++)
            cp_async16(&as[tid * STR32 + ch * 4],
                       A + (size_t)(bm + tid) * K + ch * 8);
        #pragma unroll
        for (int i = 0; i < 4; i++) {
            int ch = bchb + i;
            cp_async16(&bs[brow * STR32 + ch * 4],
                       Bt + (size_t)(bn + brow) * K + ch * 8);
        }
        CP_COMMIT();
    }

    #pragma unroll 1
    for (int chunk = 0; chunk < NCH; chunk++) {
        const int cur = chunk & 1;
        if (chunk + 1 < NCH) {
            const int nxt = cur ^ 1;
            const int k0 = (chunk + 1) * KC;
            uint32_t* as = As + nxt * A_STG32;
            uint32_t* bs = Bs + nxt * B_STG32;
            #pragma unroll
            for (int ch = 0; ch < 8; ch++)
                cp_async16(&as[tid * STR32 + ch * 4],
                           A + (size_t)(bm + tid) * K + k0 + ch * 8);
            #pragma unroll
            for (int i = 0; i < 4; i++) {
                int ch = bchb + i;
                cp_async16(&bs[brow * STR32 + ch * 4],
                           Bt + (size_t)(bn + brow) * K + k0 + ch * 8);
            }
            CP_COMMIT();
            CP_WAIT1();
        } else {
            CP_WAIT0();
        }
        __syncthreads();

        const uint32_t as_b = s_smu + (uint32_t)(cur * A_STG32 * 4) + a_off0;
        const uint32_t bs_b = s_smu + (uint32_t)((2 * A_STG32 + cur * B_STG32) * 4)
                            + b_off0;

        #pragma unroll
        for (int kk = 0; kk < KC; kk += 16) {
            uint32_t aF[2][4], bF[8][2];
            #pragma unroll
            for (int mt = 0; mt < 2; mt++)
                ldsm_x4(aF[mt][0], aF[mt][1], aF[mt][2], aF[mt][3],
                        as_b + (uint32_t)(mt * 16 * 144) + (uint32_t)(kk * 2));
            #pragma unroll
            for (int p = 0; p < 4; p++)
                ldsm_x4(bF[2*p][0], bF[2*p][1], bF[2*p+1][0], bF[2*p+1][1],
                        bs_b + (uint32_t)(p * 16 * 144) + (uint32_t)(kk * 2));
            #pragma unroll
            for (int mt = 0; mt < 2; mt++)
                #pragma unroll
                for (int nt = 0; nt < 8; nt++)
                    mma_bf16(acc[mt][nt], aF[mt], bF[nt]);
        }
        __syncthreads();
    }

    if constexpr (MODE == 2) {
        // fused SwiGLU: ntile 2j = a-cols, ntile 2j+1 = gate-cols.
        #pragma unroll
        for (int mt = 0; mt < 2; mt++) {
            #pragma unroll
            for (int j = 0; j < 4; j++) {
                int row0 = bm + wm + mt * 16 + (lane >> 2);
                int pp   = bn + j * 16;
                int f    = ((pp & ~127) >> 1) + (((pp >> 4) & 7) * 8) + (lane & 3) * 2;
                float2 ba = *(const float2*)(bias + f);
                float2 bg = *(const float2*)(bias + NHALF + f);
                float a0 = acc[mt][2*j][0] + ba.x;
                float a1 = acc[mt][2*j][1] + ba.y;
                float a2 = acc[mt][2*j][2] + ba.x;
                float a3 = acc[mt][2*j][3] + ba.y;
                float z0 = acc[mt][2*j+1][0] + bg.x;
                float z1 = acc[mt][2*j+1][1] + bg.y;
                float z2 = acc[mt][2*j+1][2] + bg.x;
                float z3 = acc[mt][2*j+1][3] + bg.y;
                *(uint32_t*)((__nv_bfloat16*)C + (size_t)row0 * NHALF + f) =
                    packbf(siluf(z0) * a0, siluf(z1) * a1);
                *(uint32_t*)((__nv_bfloat16*)C + (size_t)(row0 + 8) * NHALF + f) =
                    packbf(siluf(z2) * a2, siluf(z3) * a3);
            }
        }
    } else {
        #pragma unroll
        for (int mt = 0; mt < 2; mt++) {
            #pragma unroll
            for (int nt = 0; nt < 8; nt++) {
                int row0 = bm + wm + mt * 16 + (lane >> 2);
                int col  = bn + nt * 8 + (lane & 3) * 2;
                float2 v0 = make_float2(acc[mt][nt][0], acc[mt][nt][1]);
                float2 v1 = make_float2(acc[mt][nt][2], acc[mt][nt][3]);
                if constexpr (BIAS) {
                    float2 bb = *(const float2*)(bias + col);
                    v0.x += bb.x; v0.y += bb.y;
                    v1.x += bb.x; v1.y += bb.y;
                }
                if constexpr (RES) {
                    float2 r0 = *(const float2*)(res + (size_t)row0 * N + col);
                    float2 r1 = *(const float2*)(res + (size_t)(row0 + 8) * N + col);
                    v0.x += r0.x; v0.y += r0.y;
                    v1.x += r1.x; v1.y += r1.y;
                }
                if constexpr (MODE == 1) {
                    *(uint32_t*)(C + (size_t)row0 * N + col)       = packbf(v0.x, v0.y);
                    *(uint32_t*)(C + (size_t)(row0 + 8) * N + col) = packbf(v1.x, v1.y);
                } else {
                    *(float2*)(C + (size_t)row0 * N + col)       = v0;
                    *(float2*)(C + (size_t)(row0 + 8) * N + col) = v1;
                }
            }
        }
    }
}

__global__ __launch_bounds__(128, 4) void gemm_qkv_kernel()
{
    bf16_gemm_body<3 * ND, ND, false, false, 1, __nv_bfloat16>(g_h, g_wqkv_t, g_qkv,
                                                               nullptr, nullptr);
}
__global__ __launch_bounds__(128, 4) void gemm_o_kernel(const float* __restrict__ bo,
                                                        const float* __restrict__ x)
{
    bf16_gemm_body<ND, ND, true, true, 0, float>(g_attn, g_wo_t, g_x1, bo, x);
}
__global__ __launch_bounds__(128, 4) void gemm_ffn1_kernel(const float* __restrict__ b1)
{
    bf16_gemm_body<NFF, ND, false, false, 2, __nv_bfloat16>(g_h, g_w1_t, g_gl,
                                                            b1, nullptr);
}
__global__ __launch_bounds__(128, 4) void gemm_ffn2_kernel(const float* __restrict__ b2,
                                                           float* __restrict__ out)
{
    bf16_gemm_body<ND, NHALF, true, true, 0, float>(g_gl, g_w2_t, out, b2, g_x1);
}

// ---------------- Flash attention, full bf16 MMA (R10/12, passing) --------
#define AT_STR 72
#define ATT_SMEM ((128 + 64 + 64) * AT_STR * 2)   // 36864 B

__global__ __launch_bounds__(256) void attn_mma_kernel()
{
    extern __shared__ __align__(16) __nv_bfloat16 smb[];
    __nv_bfloat16* Qs = smb;                     // [128][72]
    __nv_bfloat16* Ks = Qs + 128 * AT_STR;       // [64][72]
    __nv_bfloat16* Vs = Ks + 64 * AT_STR;        // [64][72]

    const int tid  = threadIdx.x;
    const int warp = tid >> 5, lane = tid & 31;
    const int qb = (int)gridDim.x - 1 - (int)blockIdx.x;
    const int h  = blockIdx.y;
    const int b  = blockIdx.z;
    const int row0 = qb * 128;
    const int wrow = warp * 16;

    const uint32_t sQ = (uint32_t)__cvta_generic_to_shared(Qs);
    const uint32_t sK = (uint32_t)__cvta_generic_to_shared(Ks);
    const uint32_t sV = (uint32_t)__cvta_generic_to_shared(Vs);

    {
        int row = tid >> 1;
        int chb = (tid & 1) * 4;
        const __nv_bfloat16* qp = g_qkv + (size_t)(b * NT + row0 + row) * (3 * ND)
                                  + h * NHS;
        #pragma unroll
        for (int i = 0; i < 4; i++) {
            int ch = chb + i;
            *(uint4*)&Qs[row * AT_STR + ch * 8] = *(const uint4*)(qp + ch * 8);
        }
    }

    float oacc[8][4];
    #pragma unroll
    for (int nt = 0; nt < 8; nt++)
        #pragma unroll
        for (int t = 0; t < 4; t++) oacc[nt][t] = 0.f;

    float m0 = -1e30f, m1 = -1e30f, l0 = 0.f, l1 = 0.f;
    const float scale = 0.03608439182435161f;   // 768^-0.5

    const int grow0 = row0 + wrow + (lane >> 2);
    const int grow1 = grow0 + 8;
    const int jb_max = 2 * qb + 1;

    const int kvrow = tid >> 2;
    const int kvch  = (tid & 3) * 2;

    uint4 kpre[2], vpre[2];
    {
        size_t base = (size_t)(b * NT + kvrow) * (3 * ND) + h * NHS;
        #pragma unroll
        for (int i = 0; i < 2; i++) {
            kpre[i] = *(const uint4*)(g_qkv + base + ND + (kvch + i) * 8);
            vpre[i] = *(const uint4*)(g_qkv + base + 2 * ND + (kvch + i) * 8);
        }
    }

    const uint32_t qa_off = (uint32_t)(wrow + (lane & 15)) * 144u + ((lane >> 4) << 4);
    const uint32_t kb_off = (uint32_t)((lane & 7) + ((lane >> 4) << 3)) * 144u
                          + (((lane >> 3) & 1) << 4);
    const uint32_t vb_off = (uint32_t)((lane & 7) + (((lane >> 3) & 1) << 3)) * 144u
                          + ((lane >> 4) << 4);

    for (int jb = 0; jb <= jb_max; jb++) {
        __syncthreads();
        #pragma unroll
        for (int i = 0; i < 2; i++) {
            *(uint4*)&Ks[kvrow * AT_STR + (kvch + i) * 8] = kpre[i];
            *(uint4*)&Vs[kvrow * AT_STR + (kvch + i) * 8] = vpre[i];
        }
        __syncthreads();

        if (jb < jb_max) {
            size_t base = (size_t)(b * NT + (jb + 1) * 64 + kvrow) * (3 * ND) + h * NHS;
            #pragma unroll
            for (int i = 0; i < 2; i++) {
                kpre[i] = *(const uint4*)(g_qkv + base + ND + (kvch + i) * 8);
                vpre[i] = *(const uint4*)(g_qkv + base + 2 * ND + (kvch + i) * 8);
            }
        }

        float sacc[8][4];
        #pragma unroll
        for (int nt = 0; nt < 8; nt++)
            #pragma unroll
            for (int t = 0; t < 4; t++) sacc[nt][t] = 0.f;

        #pragma unroll
        for (int kb = 0; kb < 64; kb += 16) {
            uint32_t aF[4], bF[8][2];
            ldsm_x4(aF[0], aF[1], aF[2], aF[3], sQ + qa_off + kb * 2);
            #pragma unroll
            for (int p = 0; p < 4; p++)
                ldsm_x4(bF[2*p][0], bF[2*p][1], bF[2*p+1][0], bF[2*p+1][1],
                        sK + kb_off + (uint32_t)(p * 16 * 144) + (uint32_t)(kb * 2));
            #pragma unroll
            for (int nt = 0; nt < 8; nt++)
                mma_bf16(sacc[nt], aF, bF[nt]);
        }

        #pragma unroll
        for (int nt = 0; nt < 8; nt++) {
            int gcol = jb * 64 + nt * 8 + (lane & 3) * 2;
            float v0 = sacc[nt][0] * scale;
            float v1 = sacc[nt][1] * scale;
            float v2 = sacc[nt][2] * scale;
            float v3 = sacc[nt][3] * scale;
            if (gcol     > grow0) v0 = -1e30f;
            if (gcol + 1 > grow0) v1 = -1e30f;
            if (gcol     > grow1) v2 = -1e30f;
            if (gcol + 1 > grow1) v3 = -1e30f;
            sacc[nt][0] = v0; sacc[nt][1] = v1;
            sacc[nt][2] = v2; sacc[nt][3] = v3;
        }

        float mx0 = -1e30f, mx1 = -1e30f;
        #pragma unroll
        for (int nt = 0; nt < 8; nt++) {
            mx0 = fmaxf(mx0, fmaxf(sacc[nt][0], sacc[nt][1]));
            mx1 = fmaxf(mx1, fmaxf(sacc[nt][2], sacc[nt][3]));
        }
        mx0 = fmaxf(mx0, __shfl_xor_sync(0xffffffffu, mx0, 1));
        mx0 = fmaxf(mx0, __shfl_xor_sync(0xffffffffu, mx0, 2));
        mx1 = fmaxf(mx1, __shfl_xor_sync(0xffffffffu, mx1, 1));
        mx1 = fmaxf(mx1, __shfl_xor_sync(0xffffffffu, mx1, 2));

        float mn0 = fmaxf(m0, mx0);
        float mn1 = fmaxf(m1, mx1);

        float s0 = 0.f, s1 = 0.f;
        #pragma unroll
        for (int nt = 0; nt < 8; nt++) {
            float p0 = __expf(sacc[nt][0] - mn0);
            float p1 = __expf(sacc[nt][1] - mn0);
            float p2 = __expf(sacc[nt][2] - mn1);
            float p3 = __expf(sacc[nt][3] - mn1);
            sacc[nt][0] = p0; sacc[nt][1] = p1;
            sacc[nt][2] = p2; sacc[nt][3] = p3;
            s0 += p0 + p1;
            s1 += p2 + p3;
        }
        s0 += __shfl_xor_sync(0xffffffffu, s0, 1);
        s0 += __shfl_xor_sync(0xffffffffu, s0, 2);
        s1 += __shfl_xor_sync(0xffffffffu, s1, 1);
        s1 += __shfl_xor_sync(0xffffffffu, s1, 2);

        float al0 = __expf(m0 - mn0);
        float al1 = __expf(m1 - mn1);
        l0 = l0 * al0 + s0;
        l1 = l1 * al1 + s1;
        m0 = mn0; m1 = mn1;

        #pragma unroll
        for (int nt = 0; nt < 8; nt++) {
            oacc[nt][0] *= al0; oacc[nt][1] *= al0;
            oacc[nt][2] *= al1; oacc[nt][3] *= al1;
        }

        uint32_t aP[4][4];
        #pragma unroll
        for (int j = 0; j < 4; j++) {
            aP[j][0] = packbf(sacc[2*j][0],   sacc[2*j][1]);
            aP[j][1] = packbf(sacc[2*j][2],   sacc[2*j][3]);
            aP[j][2] = packbf(sacc[2*j+1][0], sacc[2*j+1][1]);
            aP[j][3] = packbf(sacc[2*j+1][2], sacc[2*j+1][3]);
        }

        #pragma unroll
        for (int j = 0; j < 4; j++) {
            uint32_t bV[8][2];
            #pragma unroll
            for (int p = 0; p < 4; p++)
                ldsm_x4_t(bV[2*p][0], bV[2*p][1], bV[2*p+1][0], bV[2*p+1][1],
                          sV + vb_off + (uint32_t)(j * 16 * 144) + (uint32_t)(p * 32));
            #pragma unroll
            for (int nt = 0; nt < 8; nt++)
                mma_bf16(oacc[nt], aP[j], bV[nt]);
        }
    }

    float li0 = 1.0f / l0, li1 = 1.0f / l1;
    {
        int r_g0 = b * NT + grow0;
        int r_g1 = b * NT + grow1;
        #pragma unroll
        for (int nt = 0; nt < 8; nt++) {
            int c = h * NHS + nt * 8 + (lane & 3) * 2;
            *(uint32_t*)&g_attn[(size_t)r_g0 * ND + c] =
                packbf(oacc[nt][0] * li0, oacc[nt][1] * li0);
            *(uint32_t*)&g_attn[(size_t)r_g1 * ND + c] =
                packbf(oacc[nt][2] * li1, oacc[nt][3] * li1);
        }
    }
}

// ---------------- launch ----------------
extern "C" void kernel_launch(void* const* d_in, const int* in_sizes, int n_in,
                              void* d_out, int out_size)
{
    const float* x  = (const float*)d_in[0];
    const float* Wq = (const float*)d_in[1];
    const float* Wk = (const float*)d_in[2];
    const float* Wv = (const float*)d_in[3];
    const float* Wo = (const float*)d_in[4];
    const float* bo = (const float*)d_in[5];
    const float* W1 = (const float*)d_in[6];
    const float* b1 = (const float*)d_in[7];
    const float* W2 = (const float*)d_in[8];
    const float* b2 = (const float*)d_in[9];
    const float* g1 = (const float*)d_in[10];
    const float* g2 = (const float*)d_in[11];
    float* out = (float*)d_out;

    cudaFuncSetAttribute(attn_mma_kernel, cudaFuncAttributeMaxDynamicSharedMemorySize, ATT_SMEM);
    cudaFuncSetAttribute(gemm_qkv_kernel,  cudaFuncAttributeMaxDynamicSharedMemorySize, GEMM_SMEM);
    cudaFuncSetAttribute(gemm_o_kernel,    cudaFuncAttributeMaxDynamicSharedMemorySize, GEMM_SMEM);
    cudaFuncSetAttribute(gemm_ffn1_kernel, cudaFuncAttributeMaxDynamicSharedMemorySize, GEMM_SMEM);
    cudaFuncSetAttribute(gemm_ffn2_kernel, cudaFuncAttributeMaxDynamicSharedMemorySize, GEMM_SMEM);

    pack_wqkv_kernel<<<(3 * ND * ND + 255) / 256, 256>>>(Wq, Wk, Wv);
    round_weights_kernel<<<(W1_N + 255) / 256, 256>>>(Wo, W1, W2);
    rmsnorm1_kernel<<<NBT, 256>>>(x, g1);
    gemm_qkv_kernel<<<dim3(3 * ND / 64, NBT / 128), 128, GEMM_SMEM>>>();
    attn_mma_kernel<<<dim3(NT / 128, NH, NB), 256, ATT_SMEM>>>();
    gemm_o_kernel<<<dim3(ND / 64, NBT / 128), 128, GEMM_SMEM>>>(bo, x);
    rmsnorm2_kernel<<<NBT, 256>>>(g2);
    gemm_ffn1_kernel<<<dim3(NFF / 64, NBT / 128), 128, GEMM_SMEM>>>(b1);
    gemm_ffn2_kernel<<<dim3(ND / 64, NBT / 128), 128, GEMM_SMEM>>>(b2, out);
}

// round 14
// speedup vs baseline: 1.0586x; 1.0586x over previous
#include <cuda_runtime.h>
#include <cuda_bf16.h>
#include <math.h>
#include <stdint.h>

// Problem constants
#define NB    2
#define NT    2048
#define ND    768
#define NH    12
#define NHS   64
#define NFF   3072
#define NHALF 1536
#define NBT   (NB*NT)   // 4096

// ---------------- scratch (device globals; no allocation) ----------------
__device__ __nv_bfloat16 g_h   [NBT * ND];
__device__ __nv_bfloat16 g_qkv [NBT * 3 * ND];
__device__ __nv_bfloat16 g_attn[NBT * ND];
__device__ float         g_x1  [NBT * ND];
__device__ __nv_bfloat16 g_gl  [NBT * NHALF];
__device__ __nv_bfloat16 g_wqkv_t[3 * ND * ND];   // [2304 n][768 k]
__device__ __nv_bfloat16 g_wo_t  [ND * ND];       // [768 n][768 k]
__device__ __nv_bfloat16 g_w1_t  [NFF * ND];      // [3072 packed n][768 k]
__device__ __nv_bfloat16 g_w2_t  [ND * NHALF];    // [768 n][1536 k]

// ---------------- async copy helpers ----------------
__device__ __forceinline__ void cp_async16(void* smem_dst, const void* gmem_src)
{
    uint32_t d = (uint32_t)__cvta_generic_to_shared(smem_dst);
    asm volatile("cp.async.cg.shared.global [%0], [%1], 16;\n" :: "r"(d), "l"(gmem_src));
}
#define CP_COMMIT() asm volatile("cp.async.commit_group;\n" ::: "memory")
#define CP_WAIT1()  asm volatile("cp.async.wait_group 1;\n" ::: "memory")
#define CP_WAIT0()  asm volatile("cp.async.wait_group 0;\n" ::: "memory")

// ---------------- ldmatrix ----------------
__device__ __forceinline__ void ldsm_x4(uint32_t& r0, uint32_t& r1,
                                        uint32_t& r2, uint32_t& r3, uint32_t addr)
{
    asm volatile("ldmatrix.sync.aligned.m8n8.x4.shared.b16 {%0,%1,%2,%3}, [%4];"
                 : "=r"(r0), "=r"(r1), "=r"(r2), "=r"(r3) : "r"(addr));
}
__device__ __forceinline__ void ldsm_x4_t(uint32_t& r0, uint32_t& r1,
                                          uint32_t& r2, uint32_t& r3, uint32_t addr)
{
    asm volatile("ldmatrix.sync.aligned.m8n8.x4.trans.shared.b16 {%0,%1,%2,%3}, [%4];"
                 : "=r"(r0), "=r"(r1), "=r"(r2), "=r"(r3) : "r"(addr));
}

// ---------------- BF16 MMA ----------------
__device__ __forceinline__ void mma_bf16(float* c, const uint32_t* a, const uint32_t* b)
{
    asm volatile(
        "mma.sync.aligned.m16n8k16.row.col.f32.bf16.bf16.f32 "
        "{%0,%1,%2,%3}, {%4,%5,%6,%7}, {%8,%9}, {%0,%1,%2,%3};\n"
        : "+f"(c[0]), "+f"(c[1]), "+f"(c[2]), "+f"(c[3])
        : "r"(a[0]), "r"(a[1]), "r"(a[2]), "r"(a[3]), "r"(b[0]), "r"(b[1]));
}

__device__ __forceinline__ uint32_t packbf(float lo, float hi)
{
    __nv_bfloat162 p = __floats2bfloat162_rn(lo, hi);
    return *(uint32_t*)&p;
}

__device__ __forceinline__ float siluf(float z)
{
    return z / (1.0f + __expf(-z));
}

// ---------------- merged weight prep: wqkv pack + Wo/W1/W2 transpose ------
#define WO_N (ND * ND)
#define W1_N (ND * NFF)
#define W2_N (NHALF * ND)
#define WQKV_N (3 * ND * ND)
__global__ void prep_weights_kernel(const float* __restrict__ Wq,
                                    const float* __restrict__ Wk,
                                    const float* __restrict__ Wv,
                                    const float* __restrict__ Wo,
                                    const float* __restrict__ W1,
                                    const float* __restrict__ W2)
{
    int idx = blockIdx.x * blockDim.x + threadIdx.x;
    if (idx < WQKV_N) {
        int n = idx / ND;
        int d = idx % ND;
        int m = n / ND;
        int r = n % ND;
        int h = r / NHS;
        int k = r % NHS;
        const float* W = (m == 0) ? Wq : ((m == 1) ? Wk : Wv);
        g_wqkv_t[idx] = __float2bfloat16(W[h * ND * NHS + d * NHS + k]);
    }
    if (idx < WO_N) {
        int n = idx / ND, k = idx % ND;
        g_wo_t[idx] = __float2bfloat16(Wo[k * ND + n]);
    }
    if (idx < W1_N) {
        int p = idx / ND, k = idx % ND;
        int base128 = p & ~127;
        int loc = p & 127;
        int u = loc >> 4;
        int v = loc & 15;
        int fbase = (base128 >> 1) + u * 8;
        int src = (v < 8) ? (fbase + v) : (NHALF + fbase + (v - 8));
        g_w1_t[idx] = __float2bfloat16(W1[k * NFF + src]);
    }
    if (idx < W2_N) {
        int n = idx / NHALF, k = idx % NHALF;
        g_w2_t[idx] = __float2bfloat16(W2[k * ND + n]);
    }
}

// ---------------- RMSNorm (bf16 output) ----------------
__device__ __forceinline__ void rms_body(const float* __restrict__ in,
                                         __nv_bfloat16* __restrict__ out,
                                         const float* __restrict__ g)
{
    int tid = threadIdx.x;
    float v0 = in[tid], v1 = in[tid + 256], v2 = in[tid + 512];
    float ss = v0*v0 + v1*v1 + v2*v2;
    #pragma unroll
    for (int o = 16; o; o >>= 1) ss += __shfl_xor_sync(0xffffffffu, ss, o);
    __shared__ float ws[8];
    __shared__ float s_inv;
    if ((tid & 31) == 0) ws[tid >> 5] = ss;
    __syncthreads();
    if (tid == 0) {
        float t = 0.f;
        #pragma unroll
        for (int i = 0; i < 8; i++) t += ws[i];
        float rms = sqrtf(t * (1.0f / (float)ND));
        s_inv = 1.0f / (rms + 1e-8f);
    }
    __syncthreads();
    float inv = s_inv;
    out[tid]       = __float2bfloat16(g[tid]       * v0 * inv);
    out[tid + 256] = __float2bfloat16(g[tid + 256] * v1 * inv);
    out[tid + 512] = __float2bfloat16(g[tid + 512] * v2 * inv);
}

__global__ __launch_bounds__(256) void rmsnorm1_kernel(const float* __restrict__ x,
                                                       const float* __restrict__ g)
{
    int row = blockIdx.x;
    rms_body(x + (size_t)row * ND, g_h + (size_t)row * ND, g);
}

__global__ __launch_bounds__(256) void rmsnorm2_kernel(const float* __restrict__ g)
{
    int row = blockIdx.x;
    rms_body(g_x1 + (size_t)row * ND, g_h + (size_t)row * ND, g);
}

// ---------------- BF16 GEMM: 128x128x64, cp.async + ldmatrix --------------
// STAGES=3 + DBUF (R12 proven, 2 CTAs/SM) or STAGES=2 + low-reg (3 CTAs/SM).
// MODE: 0 = fp32 out (+bias/res), 1 = bf16 out, 2 = fused-swiglu bf16 out
#define KC 64
#define STR32 36
#define STAGE32 (128 * STR32)
#define GEMM_SMEM3 (6 * STAGE32 * 4)   // 110592 B
#define GEMM_SMEM2 (4 * STAGE32 * 4)   // 73728 B

template<int N, int K, bool BIAS, bool RES, int MODE, int STAGES, bool DBUF, typename OutT>
__device__ __forceinline__ void bf16_gemm_body(const __nv_bfloat16* __restrict__ A,
                                               const __nv_bfloat16* __restrict__ Bt,
                                               OutT* __restrict__ C,
                                               const float* __restrict__ bias,
                                               const float* __restrict__ res)
{
    extern __shared__ __align__(16) uint32_t smu[];
    uint32_t* As = smu;                       // [STAGES][128][36] b32
    uint32_t* Bs = smu + STAGES * STAGE32;    // [STAGES][128][36] b32

    const int tid  = threadIdx.x;
    const int warp = tid >> 5, lane = tid & 31;
    const int wm = (warp >> 1) * 32;
    const int wn = (warp & 1) * 64;
    const int bm = blockIdx.y * 128;
    const int bn = blockIdx.x * 128;

    const uint32_t s_smu = (uint32_t)__cvta_generic_to_shared(smu);

    const int lrow = tid >> 1;
    const int lch  = (tid & 1) * 4;

    const uint32_t a_off0 = (uint32_t)(wm + (lane & 15)) * 144u + ((lane >> 4) << 4);
    const uint32_t b_off0 = (uint32_t)(wn + (lane & 7) + ((lane >> 4) << 3)) * 144u
                          + (((lane >> 3) & 1) << 4);

    float acc[2][8][4];
    #pragma unroll
    for (int i = 0; i < 2; i++)
        #pragma unroll
        for (int j = 0; j < 8; j++)
            #pragma unroll
            for (int t = 0; t < 4; t++) acc[i][j][t] = 0.f;

    const int NCH = K / KC;

    auto fill_stage = [&](int st, int k0) {
        uint32_t* as = As + st * STAGE32;
        uint32_t* bs = Bs + st * STAGE32;
        #pragma unroll
        for (int i = 0; i < 4; i++) {
            int ch = lch + i;
            cp_async16(&as[lrow * STR32 + ch * 4],
                       A  + (size_t)(bm + lrow) * K + k0 + ch * 8);
            cp_async16(&bs[lrow * STR32 + ch * 4],
                       Bt + (size_t)(bn + lrow) * K + k0 + ch * 8);
        }
        CP_COMMIT();
    };

    if constexpr (STAGES == 3) {
        fill_stage(0, 0);
        fill_stage(1, KC);

        int cur = 0, nst = 2;
        #pragma unroll 1
        for (int chunk = 0; chunk < NCH; chunk++) {
            if (chunk == NCH - 1) { CP_WAIT0(); } else { CP_WAIT1(); }
            __syncthreads();

            if (chunk + 2 < NCH)
                fill_stage(nst, (chunk + 2) * KC);

            const uint32_t as_b = s_smu + (uint32_t)(cur * STAGE32 * 4) + a_off0;
            const uint32_t bs_b = s_smu + (uint32_t)((STAGES + cur) * STAGE32 * 4) + b_off0;

            // fragment double buffer (R12)
            uint32_t aF[2][2][4], bF[2][8][2];
            #pragma unroll
            for (int mt = 0; mt < 2; mt++)
                ldsm_x4(aF[0][mt][0], aF[0][mt][1], aF[0][mt][2], aF[0][mt][3],
                        as_b + (uint32_t)(mt * 16 * 144));
            #pragma unroll
            for (int p = 0; p < 4; p++)
                ldsm_x4(bF[0][2*p][0], bF[0][2*p][1], bF[0][2*p+1][0], bF[0][2*p+1][1],
                        bs_b + (uint32_t)(p * 16 * 144));

            #pragma unroll
            for (int ki = 0; ki < 4; ki++) {
                const int pb = ki & 1;
                if (ki < 3) {
                    const uint32_t ko = (uint32_t)((ki + 1) * 32);
                    #pragma unroll
                    for (int mt = 0; mt < 2; mt++)
                        ldsm_x4(aF[pb^1][mt][0], aF[pb^1][mt][1],
                                aF[pb^1][mt][2], aF[pb^1][mt][3],
                                as_b + (uint32_t)(mt * 16 * 144) + ko);
                    #pragma unroll
                    for (int p = 0; p < 4; p++)
                        ldsm_x4(bF[pb^1][2*p][0], bF[pb^1][2*p][1],
                                bF[pb^1][2*p+1][0], bF[pb^1][2*p+1][1],
                                bs_b + (uint32_t)(p * 16 * 144) + ko);
                }
                #pragma unroll
                for (int mt = 0; mt < 2; mt++)
                    #pragma unroll
                    for (int nt = 0; nt < 8; nt++)
                        mma_bf16(acc[mt][nt], aF[pb][mt], bF[pb][nt]);
            }

            cur = (cur == 2) ? 0 : cur + 1;
            nst = (nst == 2) ? 0 : nst + 1;
        }
    } else {
        // 2-stage, low-register mainloop (R7 sync structure)
        fill_stage(0, 0);

        #pragma unroll 1
        for (int chunk = 0; chunk < NCH; chunk++) {
            const int cur = chunk & 1;
            if (chunk + 1 < NCH) {
                fill_stage(cur ^ 1, (chunk + 1) * KC);
                CP_WAIT1();
            } else {
                CP_WAIT0();
            }
            __syncthreads();

            const uint32_t as_b = s_smu + (uint32_t)(cur * STAGE32 * 4) + a_off0;
            const uint32_t bs_b = s_smu + (uint32_t)((STAGES + cur) * STAGE32 * 4) + b_off0;

            #pragma unroll
            for (int kk = 0; kk < KC; kk += 16) {
                uint32_t aF[2][4];
                #pragma unroll
                for (int mt = 0; mt < 2; mt++)
                    ldsm_x4(aF[mt][0], aF[mt][1], aF[mt][2], aF[mt][3],
                            as_b + (uint32_t)(mt * 16 * 144) + (uint32_t)(kk * 2));
                #pragma unroll
                for (int p = 0; p < 4; p++) {
                    uint32_t b0, b1, b2, b3;
                    ldsm_x4(b0, b1, b2, b3,
                            bs_b + (uint32_t)(p * 16 * 144) + (uint32_t)(kk * 2));
                    uint32_t bl[2] = {b0, b1};
                    uint32_t bh[2] = {b2, b3};
                    #pragma unroll
                    for (int mt = 0; mt < 2; mt++) {
                        mma_bf16(acc[mt][2*p],     aF[mt], bl);
                        mma_bf16(acc[mt][2*p + 1], aF[mt], bh);
                    }
                }
            }
            __syncthreads();
        }
    }

    if constexpr (MODE == 2) {
        #pragma unroll
        for (int mt = 0; mt < 2; mt++) {
            #pragma unroll
            for (int j = 0; j < 4; j++) {
                int row0 = bm + wm + mt * 16 + (lane >> 2);
                int f    = (bn >> 1) + (wn >> 1) + j * 8 + (lane & 3) * 2;
                float2 ba = *(const float2*)(bias + f);
                float2 bg = *(const float2*)(bias + NHALF + f);
                float a0 = acc[mt][2*j][0] + ba.x;
                float a1 = acc[mt][2*j][1] + ba.y;
                float a2 = acc[mt][2*j][2] + ba.x;
                float a3 = acc[mt][2*j][3] + ba.y;
                float z0 = acc[mt][2*j+1][0] + bg.x;
                float z1 = acc[mt][2*j+1][1] + bg.y;
                float z2 = acc[mt][2*j+1][2] + bg.x;
                float z3 = acc[mt][2*j+1][3] + bg.y;
                *(uint32_t*)((__nv_bfloat16*)C + (size_t)row0 * NHALF + f) =
                    packbf(siluf(z0) * a0, siluf(z1) * a1);
                *(uint32_t*)((__nv_bfloat16*)C + (size_t)(row0 + 8) * NHALF + f) =
                    packbf(siluf(z2) * a2, siluf(z3) * a3);
            }
        }
    } else {
        #pragma unroll
        for (int mt = 0; mt < 2; mt++) {
            #pragma unroll
            for (int nt = 0; nt < 8; nt++) {
                int row0 = bm + wm + mt * 16 + (lane >> 2);
                int col  = bn + wn + nt * 8 + (lane & 3) * 2;
                float2 v0 = make_float2(acc[mt][nt][0], acc[mt][nt][1]);
                float2 v1 = make_float2(acc[mt][nt][2], acc[mt][nt][3]);
                if constexpr (BIAS) {
                    float2 bb = *(const float2*)(bias + col);
                    v0.x += bb.x; v0.y += bb.y;
                    v1.x += bb.x; v1.y += bb.y;
                }
                if constexpr (RES) {
                    float2 r0 = *(const float2*)(res + (size_t)row0 * N + col);
                    float2 r1 = *(const float2*)(res + (size_t)(row0 + 8) * N + col);
                    v0.x += r0.x; v0.y += r0.y;
                    v1.x += r1.x; v1.y += r1.y;
                }
                if constexpr (MODE == 1) {
                    *(uint32_t*)(C + (size_t)row0 * N + col)       = packbf(v0.x, v0.y);
                    *(uint32_t*)(C + (size_t)(row0 + 8) * N + col) = packbf(v1.x, v1.y);
                } else {
                    *(float2*)(C + (size_t)row0 * N + col)       = v0;
                    *(float2*)(C + (size_t)(row0 + 8) * N + col) = v1;
                }
            }
        }
    }
}

// qkv: occupancy-3 experiment (2-stage, low-reg, reg cap 85)
__global__ __launch_bounds__(256, 3) void gemm_qkv_kernel()
{
    bf16_gemm_body<3 * ND, ND, false, false, 1, 2, false, __nv_bfloat16>(
        g_h, g_wqkv_t, g_qkv, nullptr, nullptr);
}
// others: proven R12 config
__global__ __launch_bounds__(256, 2) void gemm_o_kernel(const float* __restrict__ bo,
                                                        const float* __restrict__ x)
{
    bf16_gemm_body<ND, ND, true, true, 0, 3, true, float>(g_attn, g_wo_t, g_x1, bo, x);
}
__global__ __launch_bounds__(256, 2) void gemm_ffn1_kernel(const float* __restrict__ b1)
{
    bf16_gemm_body<NFF, ND, false, false, 2, 3, true, __nv_bfloat16>(g_h, g_w1_t, g_gl,
                                                                     b1, nullptr);
}
__global__ __launch_bounds__(256, 2) void gemm_ffn2_kernel(const float* __restrict__ b2,
                                                           float* __restrict__ out)
{
    bf16_gemm_body<ND, NHALF, true, true, 0, 3, true, float>(g_gl, g_w2_t, out, b2, g_x1);
}

// ---------------- Flash attention, full bf16 MMA (R12, passing) -----------
#define AT_STR 72
#define ATT_SMEM ((128 + 64 + 64) * AT_STR * 2)   // 36864 B

__global__ __launch_bounds__(256) void attn_mma_kernel()
{
    extern __shared__ __align__(16) __nv_bfloat16 smb[];
    __nv_bfloat16* Qs = smb;                     // [128][72]
    __nv_bfloat16* Ks = Qs + 128 * AT_STR;       // [64][72]
    __nv_bfloat16* Vs = Ks + 64 * AT_STR;        // [64][72]

    const int tid  = threadIdx.x;
    const int warp = tid >> 5, lane = tid & 31;
    const int qb = (int)gridDim.x - 1 - (int)blockIdx.x;
    const int h  = blockIdx.y;
    const int b  = blockIdx.z;
    const int row0 = qb * 128;
    const int wrow = warp * 16;

    const uint32_t sQ = (uint32_t)__cvta_generic_to_shared(Qs);
    const uint32_t sK = (uint32_t)__cvta_generic_to_shared(Ks);
    const uint32_t sV = (uint32_t)__cvta_generic_to_shared(Vs);

    {
        int row = tid >> 1;
        int chb = (tid & 1) * 4;
        const __nv_bfloat16* qp = g_qkv + (size_t)(b * NT + row0 + row) * (3 * ND)
                                  + h * NHS;
        #pragma unroll
        for (int i = 0; i < 4; i++) {
            int ch = chb + i;
            *(uint4*)&Qs[row * AT_STR + ch * 8] = *(const uint4*)(qp + ch * 8);
        }
    }

    float oacc[8][4];
    #pragma unroll
    for (int nt = 0; nt < 8; nt++)
        #pragma unroll
        for (int t = 0; t < 4; t++) oacc[nt][t] = 0.f;

    float m0 = -1e30f, m1 = -1e30f, l0 = 0.f, l1 = 0.f;
    const float scale = 0.03608439182435161f;   // 768^-0.5

    const int grow0 = row0 + wrow + (lane >> 2);
    const int grow1 = grow0 + 8;
    const int jb_max = 2 * qb + 1;

    const int kvrow = tid >> 2;
    const int kvch  = (tid & 3) * 2;

    uint4 kpre[2], vpre[2];
    {
        size_t base = (size_t)(b * NT + kvrow) * (3 * ND) + h * NHS;
        #pragma unroll
        for (int i = 0; i < 2; i++) {
            kpre[i] = *(const uint4*)(g_qkv + base + ND + (kvch + i) * 8);
            vpre[i] = *(const uint4*)(g_qkv + base + 2 * ND + (kvch + i) * 8);
        }
    }

    const uint32_t qa_off = (uint32_t)(wrow + (lane & 15)) * 144u + ((lane >> 4) << 4);
    const uint32_t kb_off = (uint32_t)((lane & 7) + ((lane >> 4) << 3)) * 144u
                          + (((lane >> 3) & 1) << 4);
    const uint32_t vb_off = (uint32_t)((lane & 7) + (((lane >> 3) & 1) << 3)) * 144u
                          + ((lane >> 4) << 4);

    for (int jb = 0; jb <= jb_max; jb++) {
        __syncthreads();
        #pragma unroll
        for (int i = 0; i < 2; i++) {
            *(uint4*)&Ks[kvrow * AT_STR + (kvch + i) * 8] = kpre[i];
            *(uint4*)&Vs[kvrow * AT_STR + (kvch + i) * 8] = vpre[i];
        }
        __syncthreads();

        if (jb < jb_max) {
            size_t base = (size_t)(b * NT + (jb + 1) * 64 + kvrow) * (3 * ND) + h * NHS;
            #pragma unroll
            for (int i = 0; i < 2; i++) {
                kpre[i] = *(const uint4*)(g_qkv + base + ND + (kvch + i) * 8);
                vpre[i] = *(const uint4*)(g_qkv + base + 2 * ND + (kvch + i) * 8);
            }
        }

        float sacc[8][4];
        #pragma unroll
        for (int nt = 0; nt < 8; nt++)
            #pragma unroll
            for (int t = 0; t < 4; t++) sacc[nt][t] = 0.f;

        #pragma unroll
        for (int kb = 0; kb < 64; kb += 16) {
            uint32_t aF[4], bF[8][2];
            ldsm_x4(aF[0], aF[1], aF[2], aF[3], sQ + qa_off + kb * 2);
            #pragma unroll
            for (int p = 0; p < 4; p++)
                ldsm_x4(bF[2*p][0], bF[2*p][1], bF[2*p+1][0], bF[2*p+1][1],
                        sK + kb_off + (uint32_t)(p * 16 * 144) + (uint32_t)(kb * 2));
            #pragma unroll
            for (int nt = 0; nt < 8; nt++)
                mma_bf16(sacc[nt], aF, bF[nt]);
        }

        #pragma unroll
        for (int nt = 0; nt < 8; nt++) {
            int gcol = jb * 64 + nt * 8 + (lane & 3) * 2;
            float v0 = sacc[nt][0] * scale;
            float v1 = sacc[nt][1] * scale;
            float v2 = sacc[nt][2] * scale;
            float v3 = sacc[nt][3] * scale;
            if (gcol     > grow0) v0 = -1e30f;
            if (gcol + 1 > grow0) v1 = -1e30f;
            if (gcol     > grow1) v2 = -1e30f;
            if (gcol + 1 > grow1) v3 = -1e30f;
            sacc[nt][0] = v0; sacc[nt][1] = v1;
            sacc[nt][2] = v2; sacc[nt][3] = v3;
        }

        float mx0 = -1e30f, mx1 = -1e30f;
        #pragma unroll
        for (int nt = 0; nt < 8; nt++) {
            mx0 = fmaxf(mx0, fmaxf(sacc[nt][0], sacc[nt][1]));
            mx1 = fmaxf(mx1, fmaxf(sacc[nt][2], sacc[nt][3]));
        }
        mx0 = fmaxf(mx0, __shfl_xor_sync(0xffffffffu, mx0, 1));
        mx0 = fmaxf(mx0, __shfl_xor_sync(0xffffffffu, mx0, 2));
        mx1 = fmaxf(mx1, __shfl_xor_sync(0xffffffffu, mx1, 1));
        mx1 = fmaxf(mx1, __shfl_xor_sync(0xffffffffu, mx1, 2));

        float mn0 = fmaxf(m0, mx0);
        float mn1 = fmaxf(m1, mx1);

        float s0 = 0.f, s1 = 0.f;
        #pragma unroll
        for (int nt = 0; nt < 8; nt++) {
            float p0 = __expf(sacc[nt][0] - mn0);
            float p1 = __expf(sacc[nt][1] - mn0);
            float p2 = __expf(sacc[nt][2] - mn1);
            float p3 = __expf(sacc[nt][3] - mn1);
            sacc[nt][0] = p0; sacc[nt][1] = p1;
            sacc[nt][2] = p2; sacc[nt][3] = p3;
            s0 += p0 + p1;
            s1 += p2 + p3;
        }
        s0 += __shfl_xor_sync(0xffffffffu, s0, 1);
        s0 += __shfl_xor_sync(0xffffffffu, s0, 2);
        s1 += __shfl_xor_sync(0xffffffffu, s1, 1);
        s1 += __shfl_xor_sync(0xffffffffu, s1, 2);

        float al0 = __expf(m0 - mn0);
        float al1 = __expf(m1 - mn1);
        l0 = l0 * al0 + s0;
        l1 = l1 * al1 + s1;
        m0 = mn0; m1 = mn1;

        #pragma unroll
        for (int nt = 0; nt < 8; nt++) {
            oacc[nt][0] *= al0; oacc[nt][1] *= al0;
            oacc[nt][2] *= al1; oacc[nt][3] *= al1;
        }

        uint32_t aP[4][4];
        #pragma unroll
        for (int j = 0; j < 4; j++) {
            aP[j][0] = packbf(sacc[2*j][0],   sacc[2*j][1]);
            aP[j][1] = packbf(sacc[2*j][2],   sacc[2*j][3]);
            aP[j][2] = packbf(sacc[2*j+1][0], sacc[2*j+1][1]);
            aP[j][3] = packbf(sacc[2*j+1][2], sacc[2*j+1][3]);
        }

        #pragma unroll
        for (int j = 0; j < 4; j++) {
            uint32_t bV[8][2];
            #pragma unroll
            for (int p = 0; p < 4; p++)
                ldsm_x4_t(bV[2*p][0], bV[2*p][1], bV[2*p+1][0], bV[2*p+1][1],
                          sV + vb_off + (uint32_t)(j * 16 * 144) + (uint32_t)(p * 32));
            #pragma unroll
            for (int nt = 0; nt < 8; nt++)
                mma_bf16(oacc[nt], aP[j], bV[nt]);
        }
    }

    float li0 = 1.0f / l0, li1 = 1.0f / l1;
    {
        int r_g0 = b * NT + grow0;
        int r_g1 = b * NT + grow1;
        #pragma unroll
        for (int nt = 0; nt < 8; nt++) {
            int c = h * NHS + nt * 8 + (lane & 3) * 2;
            *(uint32_t*)&g_attn[(size_t)r_g0 * ND + c] =
                packbf(oacc[nt][0] * li0, oacc[nt][1] * li0);
            *(uint32_t*)&g_attn[(size_t)r_g1 * ND + c] =
                packbf(oacc[nt][2] * li1, oacc[nt][3] * li1);
        }
    }
}

// ---------------- launch ----------------
extern "C" void kernel_launch(void* const* d_in, const int* in_sizes, int n_in,
                              void* d_out, int out_size)
{
    const float* x  = (const float*)d_in[0];
    const float* Wq = (const float*)d_in[1];
    const float* Wk = (const float*)d_in[2];
    const float* Wv = (const float*)d_in[3];
    const float* Wo = (const float*)d_in[4];
    const float* bo = (const float*)d_in[5];
    const float* W1 = (const float*)d_in[6];
    const float* b1 = (const float*)d_in[7];
    const float* W2 = (const float*)d_in[8];
    const float* b2 = (const float*)d_in[9];
    const float* g1 = (const float*)d_in[10];
    const float* g2 = (const float*)d_in[11];
    float* out = (float*)d_out;

    cudaFuncSetAttribute(attn_mma_kernel, cudaFuncAttributeMaxDynamicSharedMemorySize, ATT_SMEM);
    cudaFuncSetAttribute(gemm_qkv_kernel,  cudaFuncAttributeMaxDynamicSharedMemorySize, GEMM_SMEM2);
    cudaFuncSetAttribute(gemm_o_kernel,    cudaFuncAttributeMaxDynamicSharedMemorySize, GEMM_SMEM3);
    cudaFuncSetAttribute(gemm_ffn1_kernel, cudaFuncAttributeMaxDynamicSharedMemorySize, GEMM_SMEM3);
    cudaFuncSetAttribute(gemm_ffn2_kernel, cudaFuncAttributeMaxDynamicSharedMemorySize, GEMM_SMEM3);

    prep_weights_kernel<<<(W1_N + 255) / 256, 256>>>(Wq, Wk, Wv, Wo, W1, W2);
    rmsnorm1_kernel<<<NBT, 256>>>(x, g1);
    gemm_qkv_kernel<<<dim3(3 * ND / 128, NBT / 128), 256, GEMM_SMEM2>>>();
    attn_mma_kernel<<<dim3(NT / 128, NH, NB), 256, ATT_SMEM>>>();
    gemm_o_kernel<<<dim3(ND / 128, NBT / 128), 256, GEMM_SMEM3>>>(bo, x);
    rmsnorm2_kernel<<<NBT, 256>>>(g2);
    gemm_ffn1_kernel<<<dim3(NFF / 128, NBT / 128), 256, GEMM_SMEM3>>>(b1);
    gemm_ffn2_kernel<<<dim3(ND / 128, NBT / 128), 256, GEMM_SMEM3>>>(b2, out);
}

// round 15
// speedup vs baseline: 1.1541x; 1.0902x over previous
#include <cuda_runtime.h>
#include <cuda_bf16.h>
#include <math.h>
#include <stdint.h>

// Problem constants
#define NB    2
#define NT    2048
#define ND    768
#define NH    12
#define NHS   64
#define NFF   3072
#define NHALF 1536
#define NBT   (NB*NT)   // 4096

// ---------------- scratch (device globals; no allocation) ----------------
__device__ __nv_bfloat16 g_h   [NBT * ND];
__device__ __nv_bfloat16 g_qkv [NBT * 3 * ND];
__device__ __nv_bfloat16 g_attn[NBT * ND];
__device__ float         g_x1  [NBT * ND];
__device__ __nv_bfloat16 g_gl  [NBT * NHALF];
__device__ __nv_bfloat16 g_wqkv_t[3 * ND * ND];   // [2304 n][768 k]
__device__ __nv_bfloat16 g_wo_t  [ND * ND];       // [768 n][768 k]
__device__ __nv_bfloat16 g_w1_t  [NFF * ND];      // [3072 packed n][768 k]
__device__ __nv_bfloat16 g_w2_t  [ND * NHALF];    // [768 n][1536 k]

// ---------------- async copy helpers ----------------
__device__ __forceinline__ void cp_async16(void* smem_dst, const void* gmem_src)
{
    uint32_t d = (uint32_t)__cvta_generic_to_shared(smem_dst);
    asm volatile("cp.async.cg.shared.global [%0], [%1], 16;\n" :: "r"(d), "l"(gmem_src));
}
#define CP_COMMIT() asm volatile("cp.async.commit_group;\n" ::: "memory")
#define CP_WAIT1()  asm volatile("cp.async.wait_group 1;\n" ::: "memory")
#define CP_WAIT0()  asm volatile("cp.async.wait_group 0;\n" ::: "memory")

// ---------------- ldmatrix ----------------
__device__ __forceinline__ void ldsm_x4(uint32_t& r0, uint32_t& r1,
                                        uint32_t& r2, uint32_t& r3, uint32_t addr)
{
    asm volatile("ldmatrix.sync.aligned.m8n8.x4.shared.b16 {%0,%1,%2,%3}, [%4];"
                 : "=r"(r0), "=r"(r1), "=r"(r2), "=r"(r3) : "r"(addr));
}
__device__ __forceinline__ void ldsm_x4_t(uint32_t& r0, uint32_t& r1,
                                          uint32_t& r2, uint32_t& r3, uint32_t addr)
{
    asm volatile("ldmatrix.sync.aligned.m8n8.x4.trans.shared.b16 {%0,%1,%2,%3}, [%4];"
                 : "=r"(r0), "=r"(r1), "=r"(r2), "=r"(r3) : "r"(addr));
}

// ---------------- BF16 MMA ----------------
__device__ __forceinline__ void mma_bf16(float* c, const uint32_t* a, const uint32_t* b)
{
    asm volatile(
        "mma.sync.aligned.m16n8k16.row.col.f32.bf16.bf16.f32 "
        "{%0,%1,%2,%3}, {%4,%5,%6,%7}, {%8,%9}, {%0,%1,%2,%3};\n"
        : "+f"(c[0]), "+f"(c[1]), "+f"(c[2]), "+f"(c[3])
        : "r"(a[0]), "r"(a[1]), "r"(a[2]), "r"(a[3]), "r"(b[0]), "r"(b[1]));
}

__device__ __forceinline__ uint32_t packbf(float lo, float hi)
{
    __nv_bfloat162 p = __floats2bfloat162_rn(lo, hi);
    return *(uint32_t*)&p;
}

__device__ __forceinline__ float siluf(float z)
{
    return z / (1.0f + __expf(-z));
}

// ---------------- merged weight prep ----------------
#define WO_N (ND * ND)
#define W1_N (ND * NFF)
#define W2_N (NHALF * ND)
#define WQKV_N (3 * ND * ND)
__global__ void prep_weights_kernel(const float* __restrict__ Wq,
                                    const float* __restrict__ Wk,
                                    const float* __restrict__ Wv,
                                    const float* __restrict__ Wo,
                                    const float* __restrict__ W1,
                                    const float* __restrict__ W2)
{
    int idx = blockIdx.x * blockDim.x + threadIdx.x;
    if (idx < WQKV_N) {
        int n = idx / ND;
        int d = idx % ND;
        int m = n / ND;
        int r = n % ND;
        int h = r / NHS;
        int k = r % NHS;
        const float* W = (m == 0) ? Wq : ((m == 1) ? Wk : Wv);
        g_wqkv_t[idx] = __float2bfloat16(W[h * ND * NHS + d * NHS + k]);
    }
    if (idx < WO_N) {
        int n = idx / ND, k = idx % ND;
        g_wo_t[idx] = __float2bfloat16(Wo[k * ND + n]);
    }
    if (idx < W1_N) {
        int p = idx / ND, k = idx % ND;
        int base128 = p & ~127;
        int loc = p & 127;
        int u = loc >> 4;
        int v = loc & 15;
        int fbase = (base128 >> 1) + u * 8;
        int src = (v < 8) ? (fbase + v) : (NHALF + fbase + (v - 8));
        g_w1_t[idx] = __float2bfloat16(W1[k * NFF + src]);
    }
    if (idx < W2_N) {
        int n = idx / NHALF, k = idx % NHALF;
        g_w2_t[idx] = __float2bfloat16(W2[k * ND + n]);
    }
}

// ---------------- RMSNorm (bf16 output) ----------------
__device__ __forceinline__ void rms_body(const float* __restrict__ in,
                                         __nv_bfloat16* __restrict__ out,
                                         const float* __restrict__ g)
{
    int tid = threadIdx.x;
    float v0 = in[tid], v1 = in[tid + 256], v2 = in[tid + 512];
    float ss = v0*v0 + v1*v1 + v2*v2;
    #pragma unroll
    for (int o = 16; o; o >>= 1) ss += __shfl_xor_sync(0xffffffffu, ss, o);
    __shared__ float ws[8];
    __shared__ float s_inv;
    if ((tid & 31) == 0) ws[tid >> 5] = ss;
    __syncthreads();
    if (tid == 0) {
        float t = 0.f;
        #pragma unroll
        for (int i = 0; i < 8; i++) t += ws[i];
        float rms = sqrtf(t * (1.0f / (float)ND));
        s_inv = 1.0f / (rms + 1e-8f);
    }
    __syncthreads();
    float inv = s_inv;
    out[tid]       = __float2bfloat16(g[tid]       * v0 * inv);
    out[tid + 256] = __float2bfloat16(g[tid + 256] * v1 * inv);
    out[tid + 512] = __float2bfloat16(g[tid + 512] * v2 * inv);
}

__global__ __launch_bounds__(256) void rmsnorm1_kernel(const float* __restrict__ x,
                                                       const float* __restrict__ g)
{
    int row = blockIdx.x;
    rms_body(x + (size_t)row * ND, g_h + (size_t)row * ND, g);
}

__global__ __launch_bounds__(256) void rmsnorm2_kernel(const float* __restrict__ g)
{
    int row = blockIdx.x;
    rms_body(g_x1 + (size_t)row * ND, g_h + (size_t)row * ND, g);
}

// ---------------- BF16 GEMM: 128x128x64, 3-stage cp.async + ldmatrix ------
// R12-proven body: fragment double-buffer, 2 CTAs/SM.
// MODE: 0 = fp32 out (+bias/res), 1 = bf16 out, 2 = fused-swiglu bf16 out
#define KC 64
#define STR32 36
#define STAGE32 (128 * STR32)
#define GEMM_SMEM (6 * STAGE32 * 4)   // 110592 B

template<int N, int K, bool BIAS, bool RES, int MODE, typename OutT>
__device__ __forceinline__ void bf16_gemm_body(const __nv_bfloat16* __restrict__ A,
                                               const __nv_bfloat16* __restrict__ Bt,
                                               OutT* __restrict__ C,
                                               const float* __restrict__ bias,
                                               const float* __restrict__ res)
{
    extern __shared__ __align__(16) uint32_t smu[];
    uint32_t* As = smu;                 // [3][128][36] b32
    uint32_t* Bs = smu + 3 * STAGE32;   // [3][128][36] b32

    const int tid  = threadIdx.x;
    const int warp = tid >> 5, lane = tid & 31;
    const int wm = (warp >> 1) * 32;
    const int wn = (warp & 1) * 64;
    const int bm = blockIdx.y * 128;
    const int bn = blockIdx.x * 128;

    const uint32_t s_smu = (uint32_t)__cvta_generic_to_shared(smu);

    const int lrow = tid >> 1;
    const int lch  = (tid & 1) * 4;

    const uint32_t a_off0 = (uint32_t)(wm + (lane & 15)) * 144u + ((lane >> 4) << 4);
    const uint32_t b_off0 = (uint32_t)(wn + (lane & 7) + ((lane >> 4) << 3)) * 144u
                          + (((lane >> 3) & 1) << 4);

    float acc[2][8][4];
    #pragma unroll
    for (int i = 0; i < 2; i++)
        #pragma unroll
        for (int j = 0; j < 8; j++)
            #pragma unroll
            for (int t = 0; t < 4; t++) acc[i][j][t] = 0.f;

    const int NCH = K / KC;

    auto fill_stage = [&](int st, int k0) {
        uint32_t* as = As + st * STAGE32;
        uint32_t* bs = Bs + st * STAGE32;
        #pragma unroll
        for (int i = 0; i < 4; i++) {
            int ch = lch + i;
            cp_async16(&as[lrow * STR32 + ch * 4],
                       A  + (size_t)(bm + lrow) * K + k0 + ch * 8);
            cp_async16(&bs[lrow * STR32 + ch * 4],
                       Bt + (size_t)(bn + lrow) * K + k0 + ch * 8);
        }
        CP_COMMIT();
    };

    fill_stage(0, 0);
    fill_stage(1, KC);

    int cur = 0, nst = 2;
    #pragma unroll 1
    for (int chunk = 0; chunk < NCH; chunk++) {
        if (chunk == NCH - 1) { CP_WAIT0(); } else { CP_WAIT1(); }
        __syncthreads();

        if (chunk + 2 < NCH)
            fill_stage(nst, (chunk + 2) * KC);

        const uint32_t as_b = s_smu + (uint32_t)(cur * STAGE32 * 4) + a_off0;
        const uint32_t bs_b = s_smu + (uint32_t)((3 + cur) * STAGE32 * 4) + b_off0;

        uint32_t aF[2][2][4], bF[2][8][2];
        #pragma unroll
        for (int mt = 0; mt < 2; mt++)
            ldsm_x4(aF[0][mt][0], aF[0][mt][1], aF[0][mt][2], aF[0][mt][3],
                    as_b + (uint32_t)(mt * 16 * 144));
        #pragma unroll
        for (int p = 0; p < 4; p++)
            ldsm_x4(bF[0][2*p][0], bF[0][2*p][1], bF[0][2*p+1][0], bF[0][2*p+1][1],
                    bs_b + (uint32_t)(p * 16 * 144));

        #pragma unroll
        for (int ki = 0; ki < 4; ki++) {
            const int pb = ki & 1;
            if (ki < 3) {
                const uint32_t ko = (uint32_t)((ki + 1) * 32);
                #pragma unroll
                for (int mt = 0; mt < 2; mt++)
                    ldsm_x4(aF[pb^1][mt][0], aF[pb^1][mt][1],
                            aF[pb^1][mt][2], aF[pb^1][mt][3],
                            as_b + (uint32_t)(mt * 16 * 144) + ko);
                #pragma unroll
                for (int p = 0; p < 4; p++)
                    ldsm_x4(bF[pb^1][2*p][0], bF[pb^1][2*p][1],
                            bF[pb^1][2*p+1][0], bF[pb^1][2*p+1][1],
                            bs_b + (uint32_t)(p * 16 * 144) + ko);
            }
            #pragma unroll
            for (int mt = 0; mt < 2; mt++)
                #pragma unroll
                for (int nt = 0; nt < 8; nt++)
                    mma_bf16(acc[mt][nt], aF[pb][mt], bF[pb][nt]);
        }

        cur = (cur == 2) ? 0 : cur + 1;
        nst = (nst == 2) ? 0 : nst + 1;
    }

    if constexpr (MODE == 2) {
        #pragma unroll
        for (int mt = 0; mt < 2; mt++) {
            #pragma unroll
            for (int j = 0; j < 4; j++) {
                int row0 = bm + wm + mt * 16 + (lane >> 2);
                int f    = (bn >> 1) + (wn >> 1) + j * 8 + (lane & 3) * 2;
                float2 ba = *(const float2*)(bias + f);
                float2 bg = *(const float2*)(bias + NHALF + f);
                float a0 = acc[mt][2*j][0] + ba.x;
                float a1 = acc[mt][2*j][1] + ba.y;
                float a2 = acc[mt][2*j][2] + ba.x;
                float a3 = acc[mt][2*j][3] + ba.y;
                float z0 = acc[mt][2*j+1][0] + bg.x;
                float z1 = acc[mt][2*j+1][1] + bg.y;
                float z2 = acc[mt][2*j+1][2] + bg.x;
                float z3 = acc[mt][2*j+1][3] + bg.y;
                *(uint32_t*)((__nv_bfloat16*)C + (size_t)row0 * NHALF + f) =
                    packbf(siluf(z0) * a0, siluf(z1) * a1);
                *(uint32_t*)((__nv_bfloat16*)C + (size_t)(row0 + 8) * NHALF + f) =
                    packbf(siluf(z2) * a2, siluf(z3) * a3);
            }
        }
    } else {
        #pragma unroll
        for (int mt = 0; mt < 2; mt++) {
            #pragma unroll
            for (int nt = 0; nt < 8; nt++) {
                int row0 = bm + wm + mt * 16 + (lane >> 2);
                int col  = bn + wn + nt * 8 + (lane & 3) * 2;
                float2 v0 = make_float2(acc[mt][nt][0], acc[mt][nt][1]);
                float2 v1 = make_float2(acc[mt][nt][2], acc[mt][nt][3]);
                if constexpr (BIAS) {
                    float2 bb = *(const float2*)(bias + col);
                    v0.x += bb.x; v0.y += bb.y;
                    v1.x += bb.x; v1.y += bb.y;
                }
                if constexpr (RES) {
                    float2 r0 = *(const float2*)(res + (size_t)row0 * N + col);
                    float2 r1 = *(const float2*)(res + (size_t)(row0 + 8) * N + col);
                    v0.x += r0.x; v0.y += r0.y;
                    v1.x += r1.x; v1.y += r1.y;
                }
                if constexpr (MODE == 1) {
                    *(uint32_t*)(C + (size_t)row0 * N + col)       = packbf(v0.x, v0.y);
                    *(uint32_t*)(C + (size_t)(row0 + 8) * N + col) = packbf(v1.x, v1.y);
                } else {
                    *(float2*)(C + (size_t)row0 * N + col)       = v0;
                    *(float2*)(C + (size_t)(row0 + 8) * N + col) = v1;
                }
            }
        }
    }
}

__global__ __launch_bounds__(256, 2) void gemm_qkv_kernel()
{
    bf16_gemm_body<3 * ND, ND, false, false, 1, __nv_bfloat16>(g_h, g_wqkv_t, g_qkv,
                                                               nullptr, nullptr);
}
__global__ __launch_bounds__(256, 2) void gemm_o_kernel(const float* __restrict__ bo,
                                                        const float* __restrict__ x)
{
    bf16_gemm_body<ND, ND, true, true, 0, float>(g_attn, g_wo_t, g_x1, bo, x);
}
__global__ __launch_bounds__(256, 2) void gemm_ffn1_kernel(const float* __restrict__ b1)
{
    bf16_gemm_body<NFF, ND, false, false, 2, __nv_bfloat16>(g_h, g_w1_t, g_gl,
                                                            b1, nullptr);
}
__global__ __launch_bounds__(256, 2) void gemm_ffn2_kernel(const float* __restrict__ b2,
                                                           float* __restrict__ out)
{
    bf16_gemm_body<ND, NHALF, true, true, 0, float>(g_gl, g_w2_t, out, b2, g_x1);
}

// ---------------- Flash attention, bf16 MMA + double-buffered K/V ---------
// Smem: Q[128][72] + {K,V}x2 buffers [64][72] each = 55296 B.
// One __syncthreads per KV tile (was two).
#define AT_STR 72
#define KV_ELT (64 * AT_STR)               // elements per K (or V) buffer
#define ATT_SMEM ((128 + 4 * 64) * AT_STR * 2)   // 55296 B

__global__ __launch_bounds__(256) void attn_mma_kernel()
{
    extern __shared__ __align__(16) __nv_bfloat16 smb[];
    __nv_bfloat16* Qs = smb;                       // [128][72]
    __nv_bfloat16* KV = smb + 128 * AT_STR;        // [K0 V0 K1 V1]

    const int tid  = threadIdx.x;
    const int warp = tid >> 5, lane = tid & 31;
    const int qb = (int)gridDim.x - 1 - (int)blockIdx.x;
    const int h  = blockIdx.y;
    const int b  = blockIdx.z;
    const int row0 = qb * 128;
    const int wrow = warp * 16;

    const uint32_t sQ  = (uint32_t)__cvta_generic_to_shared(Qs);
    const uint32_t sKV = (uint32_t)__cvta_generic_to_shared(KV);

    // ---- load Q tile ----
    {
        int row = tid >> 1;
        int chb = (tid & 1) * 4;
        const __nv_bfloat16* qp = g_qkv + (size_t)(b * NT + row0 + row) * (3 * ND)
                                  + h * NHS;
        #pragma unroll
        for (int i = 0; i < 4; i++) {
            int ch = chb + i;
            *(uint4*)&Qs[row * AT_STR + ch * 8] = *(const uint4*)(qp + ch * 8);
        }
    }

    float oacc[8][4];
    #pragma unroll
    for (int nt = 0; nt < 8; nt++)
        #pragma unroll
        for (int t = 0; t < 4; t++) oacc[nt][t] = 0.f;

    float m0 = -1e30f, m1 = -1e30f, l0 = 0.f, l1 = 0.f;
    const float scale = 0.03608439182435161f;   // 768^-0.5

    const int grow0 = row0 + wrow + (lane >> 2);
    const int grow1 = grow0 + 8;
    const int jb_max = 2 * qb + 1;

    const int kvrow = tid >> 2;
    const int kvch  = (tid & 3) * 2;

    uint4 kpre[2], vpre[2];
    auto load_tile = [&](int jb) {
        size_t base = (size_t)(b * NT + jb * 64 + kvrow) * (3 * ND) + h * NHS;
        #pragma unroll
        for (int i = 0; i < 2; i++) {
            kpre[i] = *(const uint4*)(g_qkv + base + ND + (kvch + i) * 8);
            vpre[i] = *(const uint4*)(g_qkv + base + 2 * ND + (kvch + i) * 8);
        }
    };
    auto store_tile = [&](int buf) {
        __nv_bfloat16* Kb = KV + buf * 2 * KV_ELT;
        __nv_bfloat16* Vb = Kb + KV_ELT;
        #pragma unroll
        for (int i = 0; i < 2; i++) {
            *(uint4*)&Kb[kvrow * AT_STR + (kvch + i) * 8] = kpre[i];
            *(uint4*)&Vb[kvrow * AT_STR + (kvch + i) * 8] = vpre[i];
        }
    };

    // prologue: tile 0 -> buf0; prefetch tile 1
    load_tile(0);
    store_tile(0);
    if (jb_max >= 1) load_tile(1);
    __syncthreads();

    const uint32_t qa_off = (uint32_t)(wrow + (lane & 15)) * 144u + ((lane >> 4) << 4);
    const uint32_t kb_off = (uint32_t)((lane & 7) + ((lane >> 4) << 3)) * 144u
                          + (((lane >> 3) & 1) << 4);
    const uint32_t vb_off = (uint32_t)((lane & 7) + (((lane >> 3) & 1) << 3)) * 144u
                          + ((lane >> 4) << 4);

    for (int jb = 0; jb <= jb_max; jb++) {
        // store prefetched tile jb+1 into alternate buffer; prefetch jb+2
        if (jb < jb_max) {
            store_tile((jb + 1) & 1);
            if (jb + 1 < jb_max) load_tile(jb + 2);
        }

        const uint32_t kvb = (uint32_t)((jb & 1) * 2 * KV_ELT * 2);   // byte offset
        const uint32_t sKc = sKV + kvb;
        const uint32_t sVc = sKc + KV_ELT * 2;

        // ---- S = Q K^T ----
        float sacc[8][4];
        #pragma unroll
        for (int nt = 0; nt < 8; nt++)
            #pragma unroll
            for (int t = 0; t < 4; t++) sacc[nt][t] = 0.f;

        #pragma unroll
        for (int kb = 0; kb < 64; kb += 16) {
            uint32_t aF[4], bF[8][2];
            ldsm_x4(aF[0], aF[1], aF[2], aF[3], sQ + qa_off + kb * 2);
            #pragma unroll
            for (int p = 0; p < 4; p++)
                ldsm_x4(bF[2*p][0], bF[2*p][1], bF[2*p+1][0], bF[2*p+1][1],
                        sKc + kb_off + (uint32_t)(p * 16 * 144) + (uint32_t)(kb * 2));
            #pragma unroll
            for (int nt = 0; nt < 8; nt++)
                mma_bf16(sacc[nt], aF, bF[nt]);
        }

        // ---- scale + causal mask ----
        #pragma unroll
        for (int nt = 0; nt < 8; nt++) {
            int gcol = jb * 64 + nt * 8 + (lane & 3) * 2;
            float v0 = sacc[nt][0] * scale;
            float v1 = sacc[nt][1] * scale;
            float v2 = sacc[nt][2] * scale;
            float v3 = sacc[nt][3] * scale;
            if (gcol     > grow0) v0 = -1e30f;
            if (gcol + 1 > grow0) v1 = -1e30f;
            if (gcol     > grow1) v2 = -1e30f;
            if (gcol + 1 > grow1) v3 = -1e30f;
            sacc[nt][0] = v0; sacc[nt][1] = v1;
            sacc[nt][2] = v2; sacc[nt][3] = v3;
        }

        // ---- online softmax ----
        float mx0 = -1e30f, mx1 = -1e30f;
        #pragma unroll
        for (int nt = 0; nt < 8; nt++) {
            mx0 = fmaxf(mx0, fmaxf(sacc[nt][0], sacc[nt][1]));
            mx1 = fmaxf(mx1, fmaxf(sacc[nt][2], sacc[nt][3]));
        }
        mx0 = fmaxf(mx0, __shfl_xor_sync(0xffffffffu, mx0, 1));
        mx0 = fmaxf(mx0, __shfl_xor_sync(0xffffffffu, mx0, 2));
        mx1 = fmaxf(mx1, __shfl_xor_sync(0xffffffffu, mx1, 1));
        mx1 = fmaxf(mx1, __shfl_xor_sync(0xffffffffu, mx1, 2));

        float mn0 = fmaxf(m0, mx0);
        float mn1 = fmaxf(m1, mx1);

        float s0 = 0.f, s1 = 0.f;
        #pragma unroll
        for (int nt = 0; nt < 8; nt++) {
            float p0 = __expf(sacc[nt][0] - mn0);
            float p1 = __expf(sacc[nt][1] - mn0);
            float p2 = __expf(sacc[nt][2] - mn1);
            float p3 = __expf(sacc[nt][3] - mn1);
            sacc[nt][0] = p0; sacc[nt][1] = p1;
            sacc[nt][2] = p2; sacc[nt][3] = p3;
            s0 += p0 + p1;
            s1 += p2 + p3;
        }
        s0 += __shfl_xor_sync(0xffffffffu, s0, 1);
        s0 += __shfl_xor_sync(0xffffffffu, s0, 2);
        s1 += __shfl_xor_sync(0xffffffffu, s1, 1);
        s1 += __shfl_xor_sync(0xffffffffu, s1, 2);

        float al0 = __expf(m0 - mn0);
        float al1 = __expf(m1 - mn1);
        l0 = l0 * al0 + s0;
        l1 = l1 * al1 + s1;
        m0 = mn0; m1 = mn1;

        #pragma unroll
        for (int nt = 0; nt < 8; nt++) {
            oacc[nt][0] *= al0; oacc[nt][1] *= al0;
            oacc[nt][2] *= al1; oacc[nt][3] *= al1;
        }

        // ---- pack P -> bf16 A-frags (registers) ----
        uint32_t aP[4][4];
        #pragma unroll
        for (int j = 0; j < 4; j++) {
            aP[j][0] = packbf(sacc[2*j][0],   sacc[2*j][1]);
            aP[j][1] = packbf(sacc[2*j][2],   sacc[2*j][3]);
            aP[j][2] = packbf(sacc[2*j+1][0], sacc[2*j+1][1]);
            aP[j][3] = packbf(sacc[2*j+1][2], sacc[2*j+1][3]);
        }

        // ---- O += P @ V ----
        #pragma unroll
        for (int j = 0; j < 4; j++) {
            uint32_t bV[8][2];
            #pragma unroll
            for (int p = 0; p < 4; p++)
                ldsm_x4_t(bV[2*p][0], bV[2*p][1], bV[2*p+1][0], bV[2*p+1][1],
                          sVc + vb_off + (uint32_t)(j * 16 * 144) + (uint32_t)(p * 32));
            #pragma unroll
            for (int nt = 0; nt < 8; nt++)
                mma_bf16(oacc[nt], aP[j], bV[nt]);
        }

        __syncthreads();   // buf (jb&1) free for overwrite at iter jb+1
    }

    float li0 = 1.0f / l0, li1 = 1.0f / l1;
    {
        int r_g0 = b * NT + grow0;
        int r_g1 = b * NT + grow1;
        #pragma unroll
        for (int nt = 0; nt < 8; nt++) {
            int c = h * NHS + nt * 8 + (lane & 3) * 2;
            *(uint32_t*)&g_attn[(size_t)r_g0 * ND + c] =
                packbf(oacc[nt][0] * li0, oacc[nt][1] * li0);
            *(uint32_t*)&g_attn[(size_t)r_g1 * ND + c] =
                packbf(oacc[nt][2] * li1, oacc[nt][3] * li1);
        }
    }
}

// ---------------- launch ----------------
extern "C" void kernel_launch(void* const* d_in, const int* in_sizes, int n_in,
                              void* d_out, int out_size)
{
    const float* x  = (const float*)d_in[0];
    const float* Wq = (const float*)d_in[1];
    const float* Wk = (const float*)d_in[2];
    const float* Wv = (const float*)d_in[3];
    const float* Wo = (const float*)d_in[4];
    const float* bo = (const float*)d_in[5];
    const float* W1 = (const float*)d_in[6];
    const float* b1 = (const float*)d_in[7];
    const float* W2 = (const float*)d_in[8];
    const float* b2 = (const float*)d_in[9];
    const float* g1 = (const float*)d_in[10];
    const float* g2 = (const float*)d_in[11];
    float* out = (float*)d_out;

    cudaFuncSetAttribute(attn_mma_kernel, cudaFuncAttributeMaxDynamicSharedMemorySize, ATT_SMEM);
    cudaFuncSetAttribute(gemm_qkv_kernel,  cudaFuncAttributeMaxDynamicSharedMemorySize, GEMM_SMEM);
    cudaFuncSetAttribute(gemm_o_kernel,    cudaFuncAttributeMaxDynamicSharedMemorySize, GEMM_SMEM);
    cudaFuncSetAttribute(gemm_ffn1_kernel, cudaFuncAttributeMaxDynamicSharedMemorySize, GEMM_SMEM);
    cudaFuncSetAttribute(gemm_ffn2_kernel, cudaFuncAttributeMaxDynamicSharedMemorySize, GEMM_SMEM);

    prep_weights_kernel<<<(W1_N + 255) / 256, 256>>>(Wq, Wk, Wv, Wo, W1, W2);
    rmsnorm1_kernel<<<NBT, 256>>>(x, g1);
    gemm_qkv_kernel<<<dim3(3 * ND / 128, NBT / 128), 256, GEMM_SMEM>>>();
    attn_mma_kernel<<<dim3(NT / 128, NH, NB), 256, ATT_SMEM>>>();
    gemm_o_kernel<<<dim3(ND / 128, NBT / 128), 256, GEMM_SMEM>>>(bo, x);
    rmsnorm2_kernel<<<NBT, 256>>>(g2);
    gemm_ffn1_kernel<<<dim3(NFF / 128, NBT / 128), 256, GEMM_SMEM>>>(b1);
    gemm_ffn2_kernel<<<dim3(ND / 128, NBT / 128), 256, GEMM_SMEM>>>(b2, out);
}

// round 16
// speedup vs baseline: 1.1645x; 1.0090x over previous
#include <cuda_runtime.h>
#include <cuda_bf16.h>
#include <math.h>
#include <stdint.h>

// Problem constants
#define NB    2
#define NT    2048
#define ND    768
#define NH    12
#define NHS   64
#define NFF   3072
#define NHALF 1536
#define NBT   (NB*NT)   // 4096

// ---------------- scratch (device globals; no allocation) ----------------
__device__ __nv_bfloat16 g_h   [NBT * ND];
__device__ __nv_bfloat16 g_qkv [NBT * 3 * ND];
__device__ __nv_bfloat16 g_attn[NBT * ND];
__device__ float         g_x1  [NBT * ND];
__device__ __nv_bfloat16 g_gl  [NBT * NHALF];
__device__ __nv_bfloat16 g_wqkv_t[3 * ND * ND];   // [2304 n][768 k]
__device__ __nv_bfloat16 g_wo_t  [ND * ND];       // [768 n][768 k]
__device__ __nv_bfloat16 g_w1_t  [NFF * ND];      // [3072 packed n][768 k]
__device__ __nv_bfloat16 g_w2_t  [ND * NHALF];    // [768 n][1536 k]

// ---------------- async copy helpers ----------------
__device__ __forceinline__ void cp_async16(void* smem_dst, const void* gmem_src)
{
    uint32_t d = (uint32_t)__cvta_generic_to_shared(smem_dst);
    asm volatile("cp.async.cg.shared.global [%0], [%1], 16;\n" :: "r"(d), "l"(gmem_src));
}
#define CP_COMMIT() asm volatile("cp.async.commit_group;\n" ::: "memory")
#define CP_WAIT1()  asm volatile("cp.async.wait_group 1;\n" ::: "memory")
#define CP_WAIT0()  asm volatile("cp.async.wait_group 0;\n" ::: "memory")

// ---------------- ldmatrix ----------------
__device__ __forceinline__ void ldsm_x4(uint32_t& r0, uint32_t& r1,
                                        uint32_t& r2, uint32_t& r3, uint32_t addr)
{
    asm volatile("ldmatrix.sync.aligned.m8n8.x4.shared.b16 {%0,%1,%2,%3}, [%4];"
                 : "=r"(r0), "=r"(r1), "=r"(r2), "=r"(r3) : "r"(addr));
}
__device__ __forceinline__ void ldsm_x4_t(uint32_t& r0, uint32_t& r1,
                                          uint32_t& r2, uint32_t& r3, uint32_t addr)
{
    asm volatile("ldmatrix.sync.aligned.m8n8.x4.trans.shared.b16 {%0,%1,%2,%3}, [%4];"
                 : "=r"(r0), "=r"(r1), "=r"(r2), "=r"(r3) : "r"(addr));
}

// ---------------- BF16 MMA ----------------
__device__ __forceinline__ void mma_bf16(float* c, const uint32_t* a, const uint32_t* b)
{
    asm volatile(
        "mma.sync.aligned.m16n8k16.row.col.f32.bf16.bf16.f32 "
        "{%0,%1,%2,%3}, {%4,%5,%6,%7}, {%8,%9}, {%0,%1,%2,%3};\n"
        : "+f"(c[0]), "+f"(c[1]), "+f"(c[2]), "+f"(c[3])
        : "r"(a[0]), "r"(a[1]), "r"(a[2]), "r"(a[3]), "r"(b[0]), "r"(b[1]));
}

__device__ __forceinline__ uint32_t packbf(float lo, float hi)
{
    __nv_bfloat162 p = __floats2bfloat162_rn(lo, hi);
    return *(uint32_t*)&p;
}

__device__ __forceinline__ float siluf(float z)
{
    return z / (1.0f + __expf(-z));
}

// ---------------- merged weight prep ----------------
#define WO_N (ND * ND)
#define W1_N (ND * NFF)
#define W2_N (NHALF * ND)
#define WQKV_N (3 * ND * ND)
__global__ void prep_weights_kernel(const float* __restrict__ Wq,
                                    const float* __restrict__ Wk,
                                    const float* __restrict__ Wv,
                                    const float* __restrict__ Wo,
                                    const float* __restrict__ W1,
                                    const float* __restrict__ W2)
{
    int idx = blockIdx.x * blockDim.x + threadIdx.x;
    if (idx < WQKV_N) {
        int n = idx / ND;
        int d = idx % ND;
        int m = n / ND;
        int r = n % ND;
        int h = r / NHS;
        int k = r % NHS;
        const float* W = (m == 0) ? Wq : ((m == 1) ? Wk : Wv);
        g_wqkv_t[idx] = __float2bfloat16(W[h * ND * NHS + d * NHS + k]);
    }
    if (idx < WO_N) {
        int n = idx / ND, k = idx % ND;
        g_wo_t[idx] = __float2bfloat16(Wo[k * ND + n]);
    }
    if (idx < W1_N) {
        int p = idx / ND, k = idx % ND;
        int base128 = p & ~127;
        int loc = p & 127;
        int u = loc >> 4;
        int v = loc & 15;
        int fbase = (base128 >> 1) + u * 8;
        int src = (v < 8) ? (fbase + v) : (NHALF + fbase + (v - 8));
        g_w1_t[idx] = __float2bfloat16(W1[k * NFF + src]);
    }
    if (idx < W2_N) {
        int n = idx / NHALF, k = idx % NHALF;
        g_w2_t[idx] = __float2bfloat16(W2[k * ND + n]);
    }
}

// ---------------- RMSNorm (bf16 output) ----------------
__device__ __forceinline__ void rms_body(const float* __restrict__ in,
                                         __nv_bfloat16* __restrict__ out,
                                         const float* __restrict__ g)
{
    int tid = threadIdx.x;
    float v0 = in[tid], v1 = in[tid + 256], v2 = in[tid + 512];
    float ss = v0*v0 + v1*v1 + v2*v2;
    #pragma unroll
    for (int o = 16; o; o >>= 1) ss += __shfl_xor_sync(0xffffffffu, ss, o);
    __shared__ float ws[8];
    __shared__ float s_inv;
    if ((tid & 31) == 0) ws[tid >> 5] = ss;
    __syncthreads();
    if (tid == 0) {
        float t = 0.f;
        #pragma unroll
        for (int i = 0; i < 8; i++) t += ws[i];
        float rms = sqrtf(t * (1.0f / (float)ND));
        s_inv = 1.0f / (rms + 1e-8f);
    }
    __syncthreads();
    float inv = s_inv;
    out[tid]       = __float2bfloat16(g[tid]       * v0 * inv);
    out[tid + 256] = __float2bfloat16(g[tid + 256] * v1 * inv);
    out[tid + 512] = __float2bfloat16(g[tid + 512] * v2 * inv);
}

__global__ __launch_bounds__(256) void rmsnorm1_kernel(const float* __restrict__ x,
                                                       const float* __restrict__ g)
{
    int row = blockIdx.x;
    rms_body(x + (size_t)row * ND, g_h + (size_t)row * ND, g);
}

__global__ __launch_bounds__(256) void rmsnorm2_kernel(const float* __restrict__ g)
{
    int row = blockIdx.x;
    rms_body(g_x1 + (size_t)row * ND, g_h + (size_t)row * ND, g);
}

// ---------------- BF16 GEMM: 128x128x64, 3-stage cp.async + ldmatrix ------
// R12-proven body: fragment double-buffer, 2 CTAs/SM.
// MODE: 0 = fp32 out (+bias/res), 1 = bf16 out, 2 = fused-swiglu bf16 out
#define KC 64
#define STR32 36
#define STAGE32 (128 * STR32)
#define GEMM_SMEM (6 * STAGE32 * 4)   // 110592 B

template<int N, int K, bool BIAS, bool RES, int MODE, typename OutT>
__device__ __forceinline__ void bf16_gemm_body(const __nv_bfloat16* __restrict__ A,
                                               const __nv_bfloat16* __restrict__ Bt,
                                               OutT* __restrict__ C,
                                               const float* __restrict__ bias,
                                               const float* __restrict__ res)
{
    extern __shared__ __align__(16) uint32_t smu[];
    uint32_t* As = smu;                 // [3][128][36] b32
    uint32_t* Bs = smu + 3 * STAGE32;   // [3][128][36] b32

    const int tid  = threadIdx.x;
    const int warp = tid >> 5, lane = tid & 31;
    const int wm = (warp >> 1) * 32;
    const int wn = (warp & 1) * 64;
    const int bm = blockIdx.y * 128;
    const int bn = blockIdx.x * 128;

    const uint32_t s_smu = (uint32_t)__cvta_generic_to_shared(smu);

    const int lrow = tid >> 1;
    const int lch  = (tid & 1) * 4;

    const uint32_t a_off0 = (uint32_t)(wm + (lane & 15)) * 144u + ((lane >> 4) << 4);
    const uint32_t b_off0 = (uint32_t)(wn + (lane & 7) + ((lane >> 4) << 3)) * 144u
                          + (((lane >> 3) & 1) << 4);

    float acc[2][8][4];
    #pragma unroll
    for (int i = 0; i < 2; i++)
        #pragma unroll
        for (int j = 0; j < 8; j++)
            #pragma unroll
            for (int t = 0; t < 4; t++) acc[i][j][t] = 0.f;

    const int NCH = K / KC;

    auto fill_stage = [&](int st, int k0) {
        uint32_t* as = As + st * STAGE32;
        uint32_t* bs = Bs + st * STAGE32;
        #pragma unroll
        for (int i = 0; i < 4; i++) {
            int ch = lch + i;
            cp_async16(&as[lrow * STR32 + ch * 4],
                       A  + (size_t)(bm + lrow) * K + k0 + ch * 8);
            cp_async16(&bs[lrow * STR32 + ch * 4],
                       Bt + (size_t)(bn + lrow) * K + k0 + ch * 8);
        }
        CP_COMMIT();
    };

    fill_stage(0, 0);
    fill_stage(1, KC);

    int cur = 0, nst = 2;
    #pragma unroll 1
    for (int chunk = 0; chunk < NCH; chunk++) {
        if (chunk == NCH - 1) { CP_WAIT0(); } else { CP_WAIT1(); }
        __syncthreads();

        if (chunk + 2 < NCH)
            fill_stage(nst, (chunk + 2) * KC);

        const uint32_t as_b = s_smu + (uint32_t)(cur * STAGE32 * 4) + a_off0;
        const uint32_t bs_b = s_smu + (uint32_t)((3 + cur) * STAGE32 * 4) + b_off0;

        uint32_t aF[2][2][4], bF[2][8][2];
        #pragma unroll
        for (int mt = 0; mt < 2; mt++)
            ldsm_x4(aF[0][mt][0], aF[0][mt][1], aF[0][mt][2], aF[0][mt][3],
                    as_b + (uint32_t)(mt * 16 * 144));
        #pragma unroll
        for (int p = 0; p < 4; p++)
            ldsm_x4(bF[0][2*p][0], bF[0][2*p][1], bF[0][2*p+1][0], bF[0][2*p+1][1],
                    bs_b + (uint32_t)(p * 16 * 144));

        #pragma unroll
        for (int ki = 0; ki < 4; ki++) {
            const int pb = ki & 1;
            if (ki < 3) {
                const uint32_t ko = (uint32_t)((ki + 1) * 32);
                #pragma unroll
                for (int mt = 0; mt < 2; mt++)
                    ldsm_x4(aF[pb^1][mt][0], aF[pb^1][mt][1],
                            aF[pb^1][mt][2], aF[pb^1][mt][3],
                            as_b + (uint32_t)(mt * 16 * 144) + ko);
                #pragma unroll
                for (int p = 0; p < 4; p++)
                    ldsm_x4(bF[pb^1][2*p][0], bF[pb^1][2*p][1],
                            bF[pb^1][2*p+1][0], bF[pb^1][2*p+1][1],
                            bs_b + (uint32_t)(p * 16 * 144) + ko);
            }
            #pragma unroll
            for (int mt = 0; mt < 2; mt++)
                #pragma unroll
                for (int nt = 0; nt < 8; nt++)
                    mma_bf16(acc[mt][nt], aF[pb][mt], bF[pb][nt]);
        }

        cur = (cur == 2) ? 0 : cur + 1;
        nst = (nst == 2) ? 0 : nst + 1;
    }

    if constexpr (MODE == 2) {
        #pragma unroll
        for (int mt = 0; mt < 2; mt++) {
            #pragma unroll
            for (int j = 0; j < 4; j++) {
                int row0 = bm + wm + mt * 16 + (lane >> 2);
                int f    = (bn >> 1) + (wn >> 1) + j * 8 + (lane & 3) * 2;
                float2 ba = *(const float2*)(bias + f);
                float2 bg = *(const float2*)(bias + NHALF + f);
                float a0 = acc[mt][2*j][0] + ba.x;
                float a1 = acc[mt][2*j][1] + ba.y;
                float a2 = acc[mt][2*j][2] + ba.x;
                float a3 = acc[mt][2*j][3] + ba.y;
                float z0 = acc[mt][2*j+1][0] + bg.x;
                float z1 = acc[mt][2*j+1][1] + bg.y;
                float z2 = acc[mt][2*j+1][2] + bg.x;
                float z3 = acc[mt][2*j+1][3] + bg.y;
                *(uint32_t*)((__nv_bfloat16*)C + (size_t)row0 * NHALF + f) =
                    packbf(siluf(z0) * a0, siluf(z1) * a1);
                *(uint32_t*)((__nv_bfloat16*)C + (size_t)(row0 + 8) * NHALF + f) =
                    packbf(siluf(z2) * a2, siluf(z3) * a3);
            }
        }
    } else {
        #pragma unroll
        for (int mt = 0; mt < 2; mt++) {
            #pragma unroll
            for (int nt = 0; nt < 8; nt++) {
                int row0 = bm + wm + mt * 16 + (lane >> 2);
                int col  = bn + wn + nt * 8 + (lane & 3) * 2;
                float2 v0 = make_float2(acc[mt][nt][0], acc[mt][nt][1]);
                float2 v1 = make_float2(acc[mt][nt][2], acc[mt][nt][3]);
                if constexpr (BIAS) {
                    float2 bb = *(const float2*)(bias + col);
                    v0.x += bb.x; v0.y += bb.y;
                    v1.x += bb.x; v1.y += bb.y;
                }
                if constexpr (RES) {
                    float2 r0 = *(const float2*)(res + (size_t)row0 * N + col);
                    float2 r1 = *(const float2*)(res + (size_t)(row0 + 8) * N + col);
                    v0.x += r0.x; v0.y += r0.y;
                    v1.x += r1.x; v1.y += r1.y;
                }
                if constexpr (MODE == 1) {
                    *(uint32_t*)(C + (size_t)row0 * N + col)       = packbf(v0.x, v0.y);
                    *(uint32_t*)(C + (size_t)(row0 + 8) * N + col) = packbf(v1.x, v1.y);
                } else {
                    *(float2*)(C + (size_t)row0 * N + col)       = v0;
                    *(float2*)(C + (size_t)(row0 + 8) * N + col) = v1;
                }
            }
        }
    }
}

__global__ __launch_bounds__(256, 2) void gemm_qkv_kernel()
{
    bf16_gemm_body<3 * ND, ND, false, false, 1, __nv_bfloat16>(g_h, g_wqkv_t, g_qkv,
                                                               nullptr, nullptr);
}
__global__ __launch_bounds__(256, 2) void gemm_o_kernel(const float* __restrict__ bo,
                                                        const float* __restrict__ x)
{
    bf16_gemm_body<ND, ND, true, true, 0, float>(g_attn, g_wo_t, g_x1, bo, x);
}
__global__ __launch_bounds__(256, 2) void gemm_ffn1_kernel(const float* __restrict__ b1)
{
    bf16_gemm_body<NFF, ND, false, false, 2, __nv_bfloat16>(g_h, g_w1_t, g_gl,
                                                            b1, nullptr);
}
__global__ __launch_bounds__(256, 2) void gemm_ffn2_kernel(const float* __restrict__ b2,
                                                           float* __restrict__ out)
{
    bf16_gemm_body<ND, NHALF, true, true, 0, float>(g_gl, g_w2_t, out, b2, g_x1);
}

// ---------------- Flash attention, bf16 MMA, lean softmax -----------------
// Q pre-scaled by 768^-0.5 at load (folds 32 FMUL/tile into 16 ops/block).
// Causal mask applied ONLY on diagonal tiles (jb >= 2*qb): ~31 of 33 tiles
// skip 64 select ops per thread.
#define AT_STR 72
#define KV_ELT (64 * AT_STR)
#define ATT_SMEM ((128 + 4 * 64) * AT_STR * 2)   // 55296 B

__global__ __launch_bounds__(256) void attn_mma_kernel()
{
    extern __shared__ __align__(16) __nv_bfloat16 smb[];
    __nv_bfloat16* Qs = smb;                       // [128][72]
    __nv_bfloat16* KV = smb + 128 * AT_STR;        // [K0 V0 K1 V1]

    const int tid  = threadIdx.x;
    const int warp = tid >> 5, lane = tid & 31;
    const int qb = (int)gridDim.x - 1 - (int)blockIdx.x;
    const int h  = blockIdx.y;
    const int b  = blockIdx.z;
    const int row0 = qb * 128;
    const int wrow = warp * 16;

    const uint32_t sQ  = (uint32_t)__cvta_generic_to_shared(Qs);
    const uint32_t sKV = (uint32_t)__cvta_generic_to_shared(KV);

    const float scale = 0.03608439182435161f;   // 768^-0.5

    // ---- load Q tile, pre-scaled ----
    {
        int row = tid >> 1;
        int chb = (tid & 1) * 4;
        const __nv_bfloat16* qp = g_qkv + (size_t)(b * NT + row0 + row) * (3 * ND)
                                  + h * NHS;
        #pragma unroll
        for (int i = 0; i < 4; i++) {
            int ch = chb + i;
            uint4 v = *(const uint4*)(qp + ch * 8);
            __nv_bfloat162* pv = (__nv_bfloat162*)&v;
            #pragma unroll
            for (int t = 0; t < 4; t++) {
                float2 f = __bfloat1622float2(pv[t]);
                pv[t] = __floats2bfloat162_rn(f.x * scale, f.y * scale);
            }
            *(uint4*)&Qs[row * AT_STR + ch * 8] = v;
        }
    }

    float oacc[8][4];
    #pragma unroll
    for (int nt = 0; nt < 8; nt++)
        #pragma unroll
        for (int t = 0; t < 4; t++) oacc[nt][t] = 0.f;

    float m0 = -1e30f, m1 = -1e30f, l0 = 0.f, l1 = 0.f;

    const int grow0 = row0 + wrow + (lane >> 2);
    const int grow1 = grow0 + 8;
    const int jb_max = 2 * qb + 1;

    const int kvrow = tid >> 2;
    const int kvch  = (tid & 3) * 2;

    uint4 kpre[2], vpre[2];
    auto load_tile = [&](int jb) {
        size_t base = (size_t)(b * NT + jb * 64 + kvrow) * (3 * ND) + h * NHS;
        #pragma unroll
        for (int i = 0; i < 2; i++) {
            kpre[i] = *(const uint4*)(g_qkv + base + ND + (kvch + i) * 8);
            vpre[i] = *(const uint4*)(g_qkv + base + 2 * ND + (kvch + i) * 8);
        }
    };
    auto store_tile = [&](int buf) {
        __nv_bfloat16* Kb = KV + buf * 2 * KV_ELT;
        __nv_bfloat16* Vb = Kb + KV_ELT;
        #pragma unroll
        for (int i = 0; i < 2; i++) {
            *(uint4*)&Kb[kvrow * AT_STR + (kvch + i) * 8] = kpre[i];
            *(uint4*)&Vb[kvrow * AT_STR + (kvch + i) * 8] = vpre[i];
        }
    };

    load_tile(0);
    store_tile(0);
    if (jb_max >= 1) load_tile(1);
    __syncthreads();

    const uint32_t qa_off = (uint32_t)(wrow + (lane & 15)) * 144u + ((lane >> 4) << 4);
    const uint32_t kb_off = (uint32_t)((lane & 7) + ((lane >> 4) << 3)) * 144u
                          + (((lane >> 3) & 1) << 4);
    const uint32_t vb_off = (uint32_t)((lane & 7) + (((lane >> 3) & 1) << 3)) * 144u
                          + ((lane >> 4) << 4);

    for (int jb = 0; jb <= jb_max; jb++) {
        if (jb < jb_max) {
            store_tile((jb + 1) & 1);
            if (jb + 1 < jb_max) load_tile(jb + 2);
        }

        const uint32_t kvb = (uint32_t)((jb & 1) * 2 * KV_ELT * 2);
        const uint32_t sKc = sKV + kvb;
        const uint32_t sVc = sKc + KV_ELT * 2;

        // ---- S = (scale*Q) K^T ----
        float sacc[8][4];
        #pragma unroll
        for (int nt = 0; nt < 8; nt++)
            #pragma unroll
            for (int t = 0; t < 4; t++) sacc[nt][t] = 0.f;

        #pragma unroll
        for (int kb = 0; kb < 64; kb += 16) {
            uint32_t aF[4], bF[8][2];
            ldsm_x4(aF[0], aF[1], aF[2], aF[3], sQ + qa_off + kb * 2);
            #pragma unroll
            for (int p = 0; p < 4; p++)
                ldsm_x4(bF[2*p][0], bF[2*p][1], bF[2*p+1][0], bF[2*p+1][1],
                        sKc + kb_off + (uint32_t)(p * 16 * 144) + (uint32_t)(kb * 2));
            #pragma unroll
            for (int nt = 0; nt < 8; nt++)
                mma_bf16(sacc[nt], aF, bF[nt]);
        }

        // ---- causal mask: only diagonal tiles ----
        if (jb >= 2 * qb) {
            #pragma unroll
            for (int nt = 0; nt < 8; nt++) {
                int gcol = jb * 64 + nt * 8 + (lane & 3) * 2;
                if (gcol     > grow0) sacc[nt][0] = -1e30f;
                if (gcol + 1 > grow0) sacc[nt][1] = -1e30f;
                if (gcol     > grow1) sacc[nt][2] = -1e30f;
                if (gcol + 1 > grow1) sacc[nt][3] = -1e30f;
            }
        }

        // ---- online softmax ----
        float mx0 = -1e30f, mx1 = -1e30f;
        #pragma unroll
        for (int nt = 0; nt < 8; nt++) {
            mx0 = fmaxf(mx0, fmaxf(sacc[nt][0], sacc[nt][1]));
            mx1 = fmaxf(mx1, fmaxf(sacc[nt][2], sacc[nt][3]));
        }
        mx0 = fmaxf(mx0, __shfl_xor_sync(0xffffffffu, mx0, 1));
        mx0 = fmaxf(mx0, __shfl_xor_sync(0xffffffffu, mx0, 2));
        mx1 = fmaxf(mx1, __shfl_xor_sync(0xffffffffu, mx1, 1));
        mx1 = fmaxf(mx1, __shfl_xor_sync(0xffffffffu, mx1, 2));

        float mn0 = fmaxf(m0, mx0);
        float mn1 = fmaxf(m1, mx1);

        float s0 = 0.f, s1 = 0.f;
        #pragma unroll
        for (int nt = 0; nt < 8; nt++) {
            float p0 = __expf(sacc[nt][0] - mn0);
            float p1 = __expf(sacc[nt][1] - mn0);
            float p2 = __expf(sacc[nt][2] - mn1);
            float p3 = __expf(sacc[nt][3] - mn1);
            sacc[nt][0] = p0; sacc[nt][1] = p1;
            sacc[nt][2] = p2; sacc[nt][3] = p3;
            s0 += p0 + p1;
            s1 += p2 + p3;
        }
        s0 += __shfl_xor_sync(0xffffffffu, s0, 1);
        s0 += __shfl_xor_sync(0xffffffffu, s0, 2);
        s1 += __shfl_xor_sync(0xffffffffu, s1, 1);
        s1 += __shfl_xor_sync(0xffffffffu, s1, 2);

        float al0 = __expf(m0 - mn0);
        float al1 = __expf(m1 - mn1);
        l0 = l0 * al0 + s0;
        l1 = l1 * al1 + s1;
        m0 = mn0; m1 = mn1;

        #pragma unroll
        for (int nt = 0; nt < 8; nt++) {
            oacc[nt][0] *= al0; oacc[nt][1] *= al0;
            oacc[nt][2] *= al1; oacc[nt][3] *= al1;
        }

        // ---- pack P -> bf16 A-frags ----
        uint32_t aP[4][4];
        #pragma unroll
        for (int j = 0; j < 4; j++) {
            aP[j][0] = packbf(sacc[2*j][0],   sacc[2*j][1]);
            aP[j][1] = packbf(sacc[2*j][2],   sacc[2*j][3]);
            aP[j][2] = packbf(sacc[2*j+1][0], sacc[2*j+1][1]);
            aP[j][3] = packbf(sacc[2*j+1][2], sacc[2*j+1][3]);
        }

        // ---- O += P @ V ----
        #pragma unroll
        for (int j = 0; j < 4; j++) {
            uint32_t bV[8][2];
            #pragma unroll
            for (int p = 0; p < 4; p++)
                ldsm_x4_t(bV[2*p][0], bV[2*p][1], bV[2*p+1][0], bV[2*p+1][1],
                          sVc + vb_off + (uint32_t)(j * 16 * 144) + (uint32_t)(p * 32));
            #pragma unroll
            for (int nt = 0; nt < 8; nt++)
                mma_bf16(oacc[nt], aP[j], bV[nt]);
        }

        __syncthreads();
    }

    float li0 = 1.0f / l0, li1 = 1.0f / l1;
    {
        int r_g0 = b * NT + grow0;
        int r_g1 = b * NT + grow1;
        #pragma unroll
        for (int nt = 0; nt < 8; nt++) {
            int c = h * NHS + nt * 8 + (lane & 3) * 2;
            *(uint32_t*)&g_attn[(size_t)r_g0 * ND + c] =
                packbf(oacc[nt][0] * li0, oacc[nt][1] * li0);
            *(uint32_t*)&g_attn[(size_t)r_g1 * ND + c] =
                packbf(oacc[nt][2] * li1, oacc[nt][3] * li1);
        }
    }
}

// ---------------- launch ----------------
extern "C" void kernel_launch(void* const* d_in, const int* in_sizes, int n_in,
                              void* d_out, int out_size)
{
    const float* x  = (const float*)d_in[0];
    const float* Wq = (const float*)d_in[1];
    const float* Wk = (const float*)d_in[2];
    const float* Wv = (const float*)d_in[3];
    const float* Wo = (const float*)d_in[4];
    const float* bo = (const float*)d_in[5];
    const float* W1 = (const float*)d_in[6];
    const float* b1 = (const float*)d_in[7];
    const float* W2 = (const float*)d_in[8];
    const float* b2 = (const float*)d_in[9];
    const float* g1 = (const float*)d_in[10];
    const float* g2 = (const float*)d_in[11];
    float* out = (float*)d_out;

    cudaFuncSetAttribute(attn_mma_kernel, cudaFuncAttributeMaxDynamicSharedMemorySize, ATT_SMEM);
    cudaFuncSetAttribute(gemm_qkv_kernel,  cudaFuncAttributeMaxDynamicSharedMemorySize, GEMM_SMEM);
    cudaFuncSetAttribute(gemm_o_kernel,    cudaFuncAttributeMaxDynamicSharedMemorySize, GEMM_SMEM);
    cudaFuncSetAttribute(gemm_ffn1_kernel, cudaFuncAttributeMaxDynamicSharedMemorySize, GEMM_SMEM);
    cudaFuncSetAttribute(gemm_ffn2_kernel, cudaFuncAttributeMaxDynamicSharedMemorySize, GEMM_SMEM);

    prep_weights_kernel<<<(W1_N + 255) / 256, 256>>>(Wq, Wk, Wv, Wo, W1, W2);
    rmsnorm1_kernel<<<NBT, 256>>>(x, g1);
    gemm_qkv_kernel<<<dim3(3 * ND / 128, NBT / 128), 256, GEMM_SMEM>>>();
    attn_mma_kernel<<<dim3(NT / 128, NH, NB), 256, ATT_SMEM>>>();
    gemm_o_kernel<<<dim3(ND / 128, NBT / 128), 256, GEMM_SMEM>>>(bo, x);
    rmsnorm2_kernel<<<NBT, 256>>>(g2);
    gemm_ffn1_kernel<<<dim3(NFF / 128, NBT / 128), 256, GEMM_SMEM>>>(b1);
    gemm_ffn2_kernel<<<dim3(ND / 128, NBT / 128), 256, GEMM_SMEM>>>(b2, out);
}

// round 17
// speedup vs baseline: 1.1725x; 1.0069x over previous
#include <cuda_runtime.h>
#include <cuda_bf16.h>
#include <math.h>
#include <stdint.h>

// Problem constants
#define NB    2
#define NT    2048
#define ND    768
#define NH    12
#define NHS   64
#define NFF   3072
#define NHALF 1536
#define NBT   (NB*NT)   // 4096

// ---------------- scratch (device globals; no allocation) ----------------
__device__ __nv_bfloat16 g_h   [NBT * ND];
__device__ __nv_bfloat16 g_qkv [NBT * 3 * ND];
__device__ __nv_bfloat16 g_attn[NBT * ND];
__device__ float         g_x1  [NBT * ND];
__device__ __nv_bfloat16 g_gl  [NBT * NHALF];
__device__ __nv_bfloat16 g_wqkv_t[3 * ND * ND];   // [2304 n][768 k]
__device__ __nv_bfloat16 g_wo_t  [ND * ND];       // [768 n][768 k]
__device__ __nv_bfloat16 g_w1_t  [NFF * ND];      // [3072 packed n][768 k]
__device__ __nv_bfloat16 g_w2_t  [ND * NHALF];    // [768 n][1536 k]

// ---------------- async copy helpers ----------------
__device__ __forceinline__ void cp_async16(void* smem_dst, const void* gmem_src)
{
    uint32_t d = (uint32_t)__cvta_generic_to_shared(smem_dst);
    asm volatile("cp.async.cg.shared.global [%0], [%1], 16;\n" :: "r"(d), "l"(gmem_src));
}
#define CP_COMMIT() asm volatile("cp.async.commit_group;\n" ::: "memory")
#define CP_WAIT1()  asm volatile("cp.async.wait_group 1;\n" ::: "memory")
#define CP_WAIT0()  asm volatile("cp.async.wait_group 0;\n" ::: "memory")

// ---------------- ldmatrix ----------------
__device__ __forceinline__ void ldsm_x4(uint32_t& r0, uint32_t& r1,
                                        uint32_t& r2, uint32_t& r3, uint32_t addr)
{
    asm volatile("ldmatrix.sync.aligned.m8n8.x4.shared.b16 {%0,%1,%2,%3}, [%4];"
                 : "=r"(r0), "=r"(r1), "=r"(r2), "=r"(r3) : "r"(addr));
}
__device__ __forceinline__ void ldsm_x4_t(uint32_t& r0, uint32_t& r1,
                                          uint32_t& r2, uint32_t& r3, uint32_t addr)
{
    asm volatile("ldmatrix.sync.aligned.m8n8.x4.trans.shared.b16 {%0,%1,%2,%3}, [%4];"
                 : "=r"(r0), "=r"(r1), "=r"(r2), "=r"(r3) : "r"(addr));
}

// ---------------- BF16 MMA ----------------
__device__ __forceinline__ void mma_bf16(float* c, const uint32_t* a, const uint32_t* b)
{
    asm volatile(
        "mma.sync.aligned.m16n8k16.row.col.f32.bf16.bf16.f32 "
        "{%0,%1,%2,%3}, {%4,%5,%6,%7}, {%8,%9}, {%0,%1,%2,%3};\n"
        : "+f"(c[0]), "+f"(c[1]), "+f"(c[2]), "+f"(c[3])
        : "r"(a[0]), "r"(a[1]), "r"(a[2]), "r"(a[3]), "r"(b[0]), "r"(b[1]));
}

__device__ __forceinline__ uint32_t packbf(float lo, float hi)
{
    __nv_bfloat162 p = __floats2bfloat162_rn(lo, hi);
    return *(uint32_t*)&p;
}

__device__ __forceinline__ float siluf(float z)
{
    return z / (1.0f + __expf(-z));
}

// ---------------- RMSNorm body ----------------
__device__ __forceinline__ void rms_body(const float* __restrict__ in,
                                         __nv_bfloat16* __restrict__ out,
                                         const float* __restrict__ g)
{
    int tid = threadIdx.x;
    float v0 = in[tid], v1 = in[tid + 256], v2 = in[tid + 512];
    float ss = v0*v0 + v1*v1 + v2*v2;
    #pragma unroll
    for (int o = 16; o; o >>= 1) ss += __shfl_xor_sync(0xffffffffu, ss, o);
    __shared__ float ws[8];
    __shared__ float s_inv;
    if ((tid & 31) == 0) ws[tid >> 5] = ss;
    __syncthreads();
    if (tid == 0) {
        float t = 0.f;
        #pragma unroll
        for (int i = 0; i < 8; i++) t += ws[i];
        float rms = sqrtf(t * (1.0f / (float)ND));
        s_inv = 1.0f / (rms + 1e-8f);
    }
    __syncthreads();
    float inv = s_inv;
    out[tid]       = __float2bfloat16(g[tid]       * v0 * inv);
    out[tid + 256] = __float2bfloat16(g[tid + 256] * v1 * inv);
    out[tid + 512] = __float2bfloat16(g[tid + 512] * v2 * inv);
}

// ---------------- merged head: rmsnorm1 rows + weight prep ----------------
#define WO_N (ND * ND)
#define W1_N (ND * NFF)
#define W2_N (NHALF * ND)
#define WQKV_N (3 * ND * ND)
#define PREP_BLKS ((W1_N + 255) / 256)

__global__ __launch_bounds__(256) void head_kernel(const float* __restrict__ x,
                                                   const float* __restrict__ g1,
                                                   const float* __restrict__ Wq,
                                                   const float* __restrict__ Wk,
                                                   const float* __restrict__ Wv,
                                                   const float* __restrict__ Wo,
                                                   const float* __restrict__ W1,
                                                   const float* __restrict__ W2)
{
    if (blockIdx.x < NBT) {
        int row = blockIdx.x;
        rms_body(x + (size_t)row * ND, g_h + (size_t)row * ND, g1);
        return;
    }
    int idx = (blockIdx.x - NBT) * 256 + threadIdx.x;
    if (idx < WQKV_N) {
        int n = idx / ND;
        int d = idx % ND;
        int m = n / ND;
        int r = n % ND;
        int h = r / NHS;
        int k = r % NHS;
        const float* W = (m == 0) ? Wq : ((m == 1) ? Wk : Wv);
        g_wqkv_t[idx] = __float2bfloat16(W[h * ND * NHS + d * NHS + k]);
    }
    if (idx < WO_N) {
        int n = idx / ND, k = idx % ND;
        g_wo_t[idx] = __float2bfloat16(Wo[k * ND + n]);
    }
    if (idx < W1_N) {
        int p = idx / ND, k = idx % ND;
        int base128 = p & ~127;
        int loc = p & 127;
        int u = loc >> 4;
        int v = loc & 15;
        int fbase = (base128 >> 1) + u * 8;
        int src = (v < 8) ? (fbase + v) : (NHALF + fbase + (v - 8));
        g_w1_t[idx] = __float2bfloat16(W1[k * NFF + src]);
    }
    if (idx < W2_N) {
        int n = idx / NHALF, k = idx % NHALF;
        g_w2_t[idx] = __float2bfloat16(W2[k * ND + n]);
    }
}

__global__ __launch_bounds__(256) void rmsnorm2_kernel(const float* __restrict__ g)
{
    int row = blockIdx.x;
    rms_body(g_x1 + (size_t)row * ND, g_h + (size_t)row * ND, g);
}

// ---------------- BF16 GEMM: 128x128x64, 3-stage cp.async + ldmatrix ------
// R12-proven body: fragment double-buffer, 2 CTAs/SM.
// MODE: 0 = fp32 out (+bias/res), 1 = bf16 out, 2 = fused-swiglu bf16 out
#define KC 64
#define STR32 36
#define STAGE32 (128 * STR32)
#define GEMM_SMEM (6 * STAGE32 * 4)   // 110592 B

template<int N, int K, bool BIAS, bool RES, int MODE, typename OutT>
__device__ __forceinline__ void bf16_gemm_body(const __nv_bfloat16* __restrict__ A,
                                               const __nv_bfloat16* __restrict__ Bt,
                                               OutT* __restrict__ C,
                                               const float* __restrict__ bias,
                                               const float* __restrict__ res)
{
    extern __shared__ __align__(16) uint32_t smu[];
    uint32_t* As = smu;                 // [3][128][36] b32
    uint32_t* Bs = smu + 3 * STAGE32;   // [3][128][36] b32

    const int tid  = threadIdx.x;
    const int warp = tid >> 5, lane = tid & 31;
    const int wm = (warp >> 1) * 32;
    const int wn = (warp & 1) * 64;
    const int bm = blockIdx.y * 128;
    const int bn = blockIdx.x * 128;

    const uint32_t s_smu = (uint32_t)__cvta_generic_to_shared(smu);

    const int lrow = tid >> 1;
    const int lch  = (tid & 1) * 4;

    const uint32_t a_off0 = (uint32_t)(wm + (lane & 15)) * 144u + ((lane >> 4) << 4);
    const uint32_t b_off0 = (uint32_t)(wn + (lane & 7) + ((lane >> 4) << 3)) * 144u
                          + (((lane >> 3) & 1) << 4);

    float acc[2][8][4];
    #pragma unroll
    for (int i = 0; i < 2; i++)
        #pragma unroll
        for (int j = 0; j < 8; j++)
            #pragma unroll
            for (int t = 0; t < 4; t++) acc[i][j][t] = 0.f;

    const int NCH = K / KC;

    auto fill_stage = [&](int st, int k0) {
        uint32_t* as = As + st * STAGE32;
        uint32_t* bs = Bs + st * STAGE32;
        #pragma unroll
        for (int i = 0; i < 4; i++) {
            int ch = lch + i;
            cp_async16(&as[lrow * STR32 + ch * 4],
                       A  + (size_t)(bm + lrow) * K + k0 + ch * 8);
            cp_async16(&bs[lrow * STR32 + ch * 4],
                       Bt + (size_t)(bn + lrow) * K + k0 + ch * 8);
        }
        CP_COMMIT();
    };

    fill_stage(0, 0);
    fill_stage(1, KC);

    int cur = 0, nst = 2;
    #pragma unroll 1
    for (int chunk = 0; chunk < NCH; chunk++) {
        if (chunk == NCH - 1) { CP_WAIT0(); } else { CP_WAIT1(); }
        __syncthreads();

        if (chunk + 2 < NCH)
            fill_stage(nst, (chunk + 2) * KC);

        const uint32_t as_b = s_smu + (uint32_t)(cur * STAGE32 * 4) + a_off0;
        const uint32_t bs_b = s_smu + (uint32_t)((3 + cur) * STAGE32 * 4) + b_off0;

        uint32_t aF[2][2][4], bF[2][8][2];
        #pragma unroll
        for (int mt = 0; mt < 2; mt++)
            ldsm_x4(aF[0][mt][0], aF[0][mt][1], aF[0][mt][2], aF[0][mt][3],
                    as_b + (uint32_t)(mt * 16 * 144));
        #pragma unroll
        for (int p = 0; p < 4; p++)
            ldsm_x4(bF[0][2*p][0], bF[0][2*p][1], bF[0][2*p+1][0], bF[0][2*p+1][1],
                    bs_b + (uint32_t)(p * 16 * 144));

        #pragma unroll
        for (int ki = 0; ki < 4; ki++) {
            const int pb = ki & 1;
            if (ki < 3) {
                const uint32_t ko = (uint32_t)((ki + 1) * 32);
                #pragma unroll
                for (int mt = 0; mt < 2; mt++)
                    ldsm_x4(aF[pb^1][mt][0], aF[pb^1][mt][1],
                            aF[pb^1][mt][2], aF[pb^1][mt][3],
                            as_b + (uint32_t)(mt * 16 * 144) + ko);
                #pragma unroll
                for (int p = 0; p < 4; p++)
                    ldsm_x4(bF[pb^1][2*p][0], bF[pb^1][2*p][1],
                            bF[pb^1][2*p+1][0], bF[pb^1][2*p+1][1],
                            bs_b + (uint32_t)(p * 16 * 144) + ko);
            }
            #pragma unroll
            for (int mt = 0; mt < 2; mt++)
                #pragma unroll
                for (int nt = 0; nt < 8; nt++)
                    mma_bf16(acc[mt][nt], aF[pb][mt], bF[pb][nt]);
        }

        cur = (cur == 2) ? 0 : cur + 1;
        nst = (nst == 2) ? 0 : nst + 1;
    }

    if constexpr (MODE == 2) {
        #pragma unroll
        for (int mt = 0; mt < 2; mt++) {
            #pragma unroll
            for (int j = 0; j < 4; j++) {
                int row0 = bm + wm + mt * 16 + (lane >> 2);
                int f    = (bn >> 1) + (wn >> 1) + j * 8 + (lane & 3) * 2;
                float2 ba = *(const float2*)(bias + f);
                float2 bg = *(const float2*)(bias + NHALF + f);
                float a0 = acc[mt][2*j][0] + ba.x;
                float a1 = acc[mt][2*j][1] + ba.y;
                float a2 = acc[mt][2*j][2] + ba.x;
                float a3 = acc[mt][2*j][3] + ba.y;
                float z0 = acc[mt][2*j+1][0] + bg.x;
                float z1 = acc[mt][2*j+1][1] + bg.y;
                float z2 = acc[mt][2*j+1][2] + bg.x;
                float z3 = acc[mt][2*j+1][3] + bg.y;
                *(uint32_t*)((__nv_bfloat16*)C + (size_t)row0 * NHALF + f) =
                    packbf(siluf(z0) * a0, siluf(z1) * a1);
                *(uint32_t*)((__nv_bfloat16*)C + (size_t)(row0 + 8) * NHALF + f) =
                    packbf(siluf(z2) * a2, siluf(z3) * a3);
            }
        }
    } else {
        #pragma unroll
        for (int mt = 0; mt < 2; mt++) {
            #pragma unroll
            for (int nt = 0; nt < 8; nt++) {
                int row0 = bm + wm + mt * 16 + (lane >> 2);
                int col  = bn + wn + nt * 8 + (lane & 3) * 2;
                float2 v0 = make_float2(acc[mt][nt][0], acc[mt][nt][1]);
                float2 v1 = make_float2(acc[mt][nt][2], acc[mt][nt][3]);
                if constexpr (BIAS) {
                    float2 bb = *(const float2*)(bias + col);
                    v0.x += bb.x; v0.y += bb.y;
                    v1.x += bb.x; v1.y += bb.y;
                }
                if constexpr (RES) {
                    float2 r0 = *(const float2*)(res + (size_t)row0 * N + col);
                    float2 r1 = *(const float2*)(res + (size_t)(row0 + 8) * N + col);
                    v0.x += r0.x; v0.y += r0.y;
                    v1.x += r1.x; v1.y += r1.y;
                }
                if constexpr (MODE == 1) {
                    *(uint32_t*)(C + (size_t)row0 * N + col)       = packbf(v0.x, v0.y);
                    *(uint32_t*)(C + (size_t)(row0 + 8) * N + col) = packbf(v1.x, v1.y);
                } else {
                    *(float2*)(C + (size_t)row0 * N + col)       = v0;
                    *(float2*)(C + (size_t)(row0 + 8) * N + col) = v1;
                }
            }
        }
    }
}

__global__ __launch_bounds__(256, 2) void gemm_qkv_kernel()
{
    bf16_gemm_body<3 * ND, ND, false, false, 1, __nv_bfloat16>(g_h, g_wqkv_t, g_qkv,
                                                               nullptr, nullptr);
}
__global__ __launch_bounds__(256, 2) void gemm_o_kernel(const float* __restrict__ bo,
                                                        const float* __restrict__ x)
{
    bf16_gemm_body<ND, ND, true, true, 0, float>(g_attn, g_wo_t, g_x1, bo, x);
}
__global__ __launch_bounds__(256, 2) void gemm_ffn1_kernel(const float* __restrict__ b1)
{
    bf16_gemm_body<NFF, ND, false, false, 2, __nv_bfloat16>(g_h, g_w1_t, g_gl,
                                                            b1, nullptr);
}
__global__ __launch_bounds__(256, 2) void gemm_ffn2_kernel(const float* __restrict__ b2,
                                                           float* __restrict__ out)
{
    bf16_gemm_body<ND, NHALF, true, true, 0, float>(g_gl, g_w2_t, out, b2, g_x1);
}

// ---------------- Flash attention, bf16 MMA, log2-domain softmax ----------
// Q pre-scaled by 768^-0.5 * log2(e): scores arrive in log2 units, so
// p = exp2f(s - m) and al = exp2f(dm) are bare MUFU.EX2 (no FMUL).
// Causal mask only on diagonal tiles (jb >= 2*qb).
#define AT_STR 72
#define KV_ELT (64 * AT_STR)
#define ATT_SMEM ((128 + 4 * 64) * AT_STR * 2)   // 55296 B

__global__ __launch_bounds__(256) void attn_mma_kernel()
{
    extern __shared__ __align__(16) __nv_bfloat16 smb[];
    __nv_bfloat16* Qs = smb;                       // [128][72]
    __nv_bfloat16* KV = smb + 128 * AT_STR;        // [K0 V0 K1 V1]

    const int tid  = threadIdx.x;
    const int warp = tid >> 5, lane = tid & 31;
    const int qb = (int)gridDim.x - 1 - (int)blockIdx.x;
    const int h  = blockIdx.y;
    const int b  = blockIdx.z;
    const int row0 = qb * 128;
    const int wrow = warp * 16;

    const uint32_t sQ  = (uint32_t)__cvta_generic_to_shared(Qs);
    const uint32_t sKV = (uint32_t)__cvta_generic_to_shared(KV);

    const float qscale = 0.03608439182435161f * 1.4426950408889634f;  // 768^-0.5 * log2e

    // ---- load Q tile, pre-scaled into log2 domain ----
    {
        int row = tid >> 1;
        int chb = (tid & 1) * 4;
        const __nv_bfloat16* qp = g_qkv + (size_t)(b * NT + row0 + row) * (3 * ND)
                                  + h * NHS;
        #pragma unroll
        for (int i = 0; i < 4; i++) {
            int ch = chb + i;
            uint4 v = *(const uint4*)(qp + ch * 8);
            __nv_bfloat162* pv = (__nv_bfloat162*)&v;
            #pragma unroll
            for (int t = 0; t < 4; t++) {
                float2 f = __bfloat1622float2(pv[t]);
                pv[t] = __floats2bfloat162_rn(f.x * qscale, f.y * qscale);
            }
            *(uint4*)&Qs[row * AT_STR + ch * 8] = v;
        }
    }

    float oacc[8][4];
    #pragma unroll
    for (int nt = 0; nt < 8; nt++)
        #pragma unroll
        for (int t = 0; t < 4; t++) oacc[nt][t] = 0.f;

    float m0 = -1e30f, m1 = -1e30f, l0 = 0.f, l1 = 0.f;

    const int grow0 = row0 + wrow + (lane >> 2);
    const int grow1 = grow0 + 8;
    const int jb_max = 2 * qb + 1;

    const int kvrow = tid >> 2;
    const int kvch  = (tid & 3) * 2;

    uint4 kpre[2], vpre[2];
    auto load_tile = [&](int jb) {
        size_t base = (size_t)(b * NT + jb * 64 + kvrow) * (3 * ND) + h * NHS;
        #pragma unroll
        for (int i = 0; i < 2; i++) {
            kpre[i] = *(const uint4*)(g_qkv + base + ND + (kvch + i) * 8);
            vpre[i] = *(const uint4*)(g_qkv + base + 2 * ND + (kvch + i) * 8);
        }
    };
    auto store_tile = [&](int buf) {
        __nv_bfloat16* Kb = KV + buf * 2 * KV_ELT;
        __nv_bfloat16* Vb = Kb + KV_ELT;
        #pragma unroll
        for (int i = 0; i < 2; i++) {
            *(uint4*)&Kb[kvrow * AT_STR + (kvch + i) * 8] = kpre[i];
            *(uint4*)&Vb[kvrow * AT_STR + (kvch + i) * 8] = vpre[i];
        }
    };

    load_tile(0);
    store_tile(0);
    if (jb_max >= 1) load_tile(1);
    __syncthreads();

    const uint32_t qa_off = (uint32_t)(wrow + (lane & 15)) * 144u + ((lane >> 4) << 4);
    const uint32_t kb_off = (uint32_t)((lane & 7) + ((lane >> 4) << 3)) * 144u
                          + (((lane >> 3) & 1) << 4);
    const uint32_t vb_off = (uint32_t)((lane & 7) + (((lane >> 3) & 1) << 3)) * 144u
                          + ((lane >> 4) << 4);

    for (int jb = 0; jb <= jb_max; jb++) {
        if (jb < jb_max) {
            store_tile((jb + 1) & 1);
            if (jb + 1 < jb_max) load_tile(jb + 2);
        }

        const uint32_t kvb = (uint32_t)((jb & 1) * 2 * KV_ELT * 2);
        const uint32_t sKc = sKV + kvb;
        const uint32_t sVc = sKc + KV_ELT * 2;

        // ---- S = (qscale*Q) K^T  (log2-domain scores) ----
        float sacc[8][4];
        #pragma unroll
        for (int nt = 0; nt < 8; nt++)
            #pragma unroll
            for (int t = 0; t < 4; t++) sacc[nt][t] = 0.f;

        #pragma unroll
        for (int kb = 0; kb < 64; kb += 16) {
            uint32_t aF[4], bF[8][2];
            ldsm_x4(aF[0], aF[1], aF[2], aF[3], sQ + qa_off + kb * 2);
            #pragma unroll
            for (int p = 0; p < 4; p++)
                ldsm_x4(bF[2*p][0], bF[2*p][1], bF[2*p+1][0], bF[2*p+1][1],
                        sKc + kb_off + (uint32_t)(p * 16 * 144) + (uint32_t)(kb * 2));
            #pragma unroll
            for (int nt = 0; nt < 8; nt++)
                mma_bf16(sacc[nt], aF, bF[nt]);
        }

        // ---- causal mask: only diagonal tiles ----
        if (jb >= 2 * qb) {
            #pragma unroll
            for (int nt = 0; nt < 8; nt++) {
                int gcol = jb * 64 + nt * 8 + (lane & 3) * 2;
                if (gcol     > grow0) sacc[nt][0] = -1e30f;
                if (gcol + 1 > grow0) sacc[nt][1] = -1e30f;
                if (gcol     > grow1) sacc[nt][2] = -1e30f;
                if (gcol + 1 > grow1) sacc[nt][3] = -1e30f;
            }
        }

        // ---- online softmax (log2 domain) ----
        float mx0 = -1e30f, mx1 = -1e30f;
        #pragma unroll
        for (int nt = 0; nt < 8; nt++) {
            mx0 = fmaxf(mx0, fmaxf(sacc[nt][0], sacc[nt][1]));
            mx1 = fmaxf(mx1, fmaxf(sacc[nt][2], sacc[nt][3]));
        }
        mx0 = fmaxf(mx0, __shfl_xor_sync(0xffffffffu, mx0, 1));
        mx0 = fmaxf(mx0, __shfl_xor_sync(0xffffffffu, mx0, 2));
        mx1 = fmaxf(mx1, __shfl_xor_sync(0xffffffffu, mx1, 1));
        mx1 = fmaxf(mx1, __shfl_xor_sync(0xffffffffu, mx1, 2));

        float mn0 = fmaxf(m0, mx0);
        float mn1 = fmaxf(m1, mx1);

        float s0 = 0.f, s1 = 0.f;
        #pragma unroll
        for (int nt = 0; nt < 8; nt++) {
            float p0 = exp2f(sacc[nt][0] - mn0);
            float p1 = exp2f(sacc[nt][1] - mn0);
            float p2 = exp2f(sacc[nt][2] - mn1);
            float p3 = exp2f(sacc[nt][3] - mn1);
            sacc[nt][0] = p0; sacc[nt][1] = p1;
            sacc[nt][2] = p2; sacc[nt][3] = p3;
            s0 += p0 + p1;
            s1 += p2 + p3;
        }
        s0 += __shfl_xor_sync(0xffffffffu, s0, 1);
        s0 += __shfl_xor_sync(0xffffffffu, s0, 2);
        s1 += __shfl_xor_sync(0xffffffffu, s1, 1);
        s1 += __shfl_xor_sync(0xffffffffu, s1, 2);

        float al0 = exp2f(m0 - mn0);
        float al1 = exp2f(m1 - mn1);
        l0 = l0 * al0 + s0;
        l1 = l1 * al1 + s1;
        m0 = mn0; m1 = mn1;

        #pragma unroll
        for (int nt = 0; nt < 8; nt++) {
            oacc[nt][0] *= al0; oacc[nt][1] *= al0;
            oacc[nt][2] *= al1; oacc[nt][3] *= al1;
        }

        // ---- pack P -> bf16 A-frags ----
        uint32_t aP[4][4];
        #pragma unroll
        for (int j = 0; j < 4; j++) {
            aP[j][0] = packbf(sacc[2*j][0],   sacc[2*j][1]);
            aP[j][1] = packbf(sacc[2*j][2],   sacc[2*j][3]);
            aP[j][2] = packbf(sacc[2*j+1][0], sacc[2*j+1][1]);
            aP[j][3] = packbf(sacc[2*j+1][2], sacc[2*j+1][3]);
        }

        // ---- O += P @ V ----
        #pragma unroll
        for (int j = 0; j < 4; j++) {
            uint32_t bV[8][2];
            #pragma unroll
            for (int p = 0; p < 4; p++)
                ldsm_x4_t(bV[2*p][0], bV[2*p][1], bV[2*p+1][0], bV[2*p+1][1],
                          sVc + vb_off + (uint32_t)(j * 16 * 144) + (uint32_t)(p * 32));
            #pragma unroll
            for (int nt = 0; nt < 8; nt++)
                mma_bf16(oacc[nt], aP[j], bV[nt]);
        }

        __syncthreads();
    }

    float li0 = 1.0f / l0, li1 = 1.0f / l1;
    {
        int r_g0 = b * NT + grow0;
        int r_g1 = b * NT + grow1;
        #pragma unroll
        for (int nt = 0; nt < 8; nt++) {
            int c = h * NHS + nt * 8 + (lane & 3) * 2;
            *(uint32_t*)&g_attn[(size_t)r_g0 * ND + c] =
                packbf(oacc[nt][0] * li0, oacc[nt][1] * li0);
            *(uint32_t*)&g_attn[(size_t)r_g1 * ND + c] =
                packbf(oacc[nt][2] * li1, oacc[nt][3] * li1);
        }
    }
}

// ---------------- launch ----------------
extern "C" void kernel_launch(void* const* d_in, const int* in_sizes, int n_in,
                              void* d_out, int out_size)
{
    const float* x  = (const float*)d_in[0];
    const float* Wq = (const float*)d_in[1];
    const float* Wk = (const float*)d_in[2];
    const float* Wv = (const float*)d_in[3];
    const float* Wo = (const float*)d_in[4];
    const float* bo = (const float*)d_in[5];
    const float* W1 = (const float*)d_in[6];
    const float* b1 = (const float*)d_in[7];
    const float* W2 = (const float*)d_in[8];
    const float* b2 = (const float*)d_in[9];
    const float* g1 = (const float*)d_in[10];
    const float* g2 = (const float*)d_in[11];
    float* out = (float*)d_out;

    cudaFuncSetAttribute(attn_mma_kernel, cudaFuncAttributeMaxDynamicSharedMemorySize, ATT_SMEM);
    cudaFuncSetAttribute(gemm_qkv_kernel,  cudaFuncAttributeMaxDynamicSharedMemorySize, GEMM_SMEM);
    cudaFuncSetAttribute(gemm_o_kernel,    cudaFuncAttributeMaxDynamicSharedMemorySize, GEMM_SMEM);
    cudaFuncSetAttribute(gemm_ffn1_kernel, cudaFuncAttributeMaxDynamicSharedMemorySize, GEMM_SMEM);
    cudaFuncSetAttribute(gemm_ffn2_kernel, cudaFuncAttributeMaxDynamicSharedMemorySize, GEMM_SMEM);

    head_kernel<<<NBT + PREP_BLKS, 256>>>(x, g1, Wq, Wk, Wv, Wo, W1, W2);
    gemm_qkv_kernel<<<dim3(3 * ND / 128, NBT / 128), 256, GEMM_SMEM>>>();
    attn_mma_kernel<<<dim3(NT / 128, NH, NB), 256, ATT_SMEM>>>();
    gemm_o_kernel<<<dim3(ND / 128, NBT / 128), 256, GEMM_SMEM>>>(bo, x);
    rmsnorm2_kernel<<<NBT, 256>>>(g2);
    gemm_ffn1_kernel<<<dim3(NFF / 128, NBT / 128), 256, GEMM_SMEM>>>(b1);
    gemm_ffn2_kernel<<<dim3(ND / 128, NBT / 128), 256, GEMM_SMEM>>>(b2, out);
}